// round 5
// baseline (speedup 1.0000x reference)
#include <cuda_runtime.h>
#include <cuda_bf16.h>
#include <cstdint>
#include <math.h>

#define NB 4
#define SS 2048
#define DD 1024
#define NEGV (-1e10f)

// ---------------------------------------------------------------------------
// Device-global scratch (allocation-free per harness rules)
// ---------------------------------------------------------------------------
__device__ __align__(128) __nv_bfloat16 g_Qh[NB*SS*DD], g_Ql[NB*SS*DD];
__device__ __align__(128) __nv_bfloat16 g_Kh[NB*SS*DD], g_Kl[NB*SS*DD];
__device__ __align__(128) __nv_bfloat16 g_Vh[NB*SS*DD], g_Vl[NB*SS*DD];
__device__ __align__(128) __nv_bfloat16 g_Wqh[DD*DD], g_Wql[DD*DD];
__device__ __align__(128) __nv_bfloat16 g_Wkh[DD*DD], g_Wkl[DD*DD];
__device__ __align__(128) __nv_bfloat16 g_Wvh[DD*DD], g_Wvl[DD*DD];
__device__ __align__(128) __nv_bfloat16 g_qh[NB*SS*DD], g_ql[NB*SS*DD];
__device__ __align__(128) __nv_bfloat16 g_kh[NB*SS*DD], g_kl[NB*SS*DD];
__device__ __align__(128) __nv_bfloat16 g_vth[NB*DD*SS], g_vtl[NB*DD*SS]; // [b][d][s]
__device__ float         g_p[(size_t)NB*SS*SS];                           // fp32 scores
__device__ __align__(128) __nv_bfloat16 g_ph[(size_t)NB*SS*SS], g_pl[(size_t)NB*SS*SS];

// ---------------------------------------------------------------------------
// helpers
// ---------------------------------------------------------------------------
__device__ __forceinline__ uint32_t s2u(const void* p) {
    return (uint32_t)__cvta_generic_to_shared(p);
}
__device__ __forceinline__ void cp16(uint32_t dst, const void* src) {
    asm volatile("cp.async.cg.shared.global [%0], [%1], 16;\n"
                 :: "r"(dst), "l"(src) : "memory");
}
__device__ __forceinline__ void cp_commit() {
    asm volatile("cp.async.commit_group;\n" ::: "memory");
}
__device__ __forceinline__ void cp_wait2() {
    asm volatile("cp.async.wait_group 2;\n" ::: "memory");
}
__device__ __forceinline__ uint32_t ld32s(uint32_t a) {
    uint32_t v;
    asm volatile("ld.shared.b32 %0, [%1];" : "=r"(v) : "r"(a));
    return v;
}
__device__ __forceinline__ void mma16816(float* c, const uint32_t* a, const uint32_t* b) {
    asm volatile("mma.sync.aligned.m16n8k16.row.col.f32.bf16.bf16.f32 "
        "{%0,%1,%2,%3}, {%4,%5,%6,%7}, {%8,%9}, {%0,%1,%2,%3};"
        : "+f"(c[0]), "+f"(c[1]), "+f"(c[2]), "+f"(c[3])
        : "r"(a[0]), "r"(a[1]), "r"(a[2]), "r"(a[3]), "r"(b[0]), "r"(b[1]));
}
__device__ __forceinline__ uint32_t pk(__nv_bfloat16 a, __nv_bfloat16 b) {
    __nv_bfloat162 t(a, b);
    return *reinterpret_cast<uint32_t*>(&t);
}

// ---------------------------------------------------------------------------
// One-shot fp32 -> (bf16 hi, bf16 lo) split for all 6 tensors.
// Each thread handles 4 consecutive float4s (MLP=4, fully coalesced).
// ---------------------------------------------------------------------------
__global__ __launch_bounds__(256) void cvt_all(
    const float* __restrict__ Q, const float* __restrict__ K,
    const float* __restrict__ V, const float* __restrict__ Wq,
    const float* __restrict__ Wk, const float* __restrict__ Wv)
{
    const int seg = blockIdx.y;
    const float* src; __nv_bfloat16 *h, *l; int n4;
    if      (seg == 0) { src = Q;  h = g_Qh;  l = g_Ql;  n4 = NB*SS*DD/4; }
    else if (seg == 1) { src = K;  h = g_Kh;  l = g_Kl;  n4 = NB*SS*DD/4; }
    else if (seg == 2) { src = V;  h = g_Vh;  l = g_Vl;  n4 = NB*SS*DD/4; }
    else if (seg == 3) { src = Wq; h = g_Wqh; l = g_Wql; n4 = DD*DD/4; }
    else if (seg == 4) { src = Wk; h = g_Wkh; l = g_Wkl; n4 = DD*DD/4; }
    else               { src = Wv; h = g_Wvh; l = g_Wvl; n4 = DD*DD/4; }

    const int base = (blockIdx.x * 256 + threadIdx.x) * 4;
    if (base >= n4) return;
    float4 v[4];
    #pragma unroll
    for (int i = 0; i < 4; i++) v[i] = reinterpret_cast<const float4*>(src)[base + i];
    #pragma unroll
    for (int i = 0; i < 4; i++) {
        __nv_bfloat16 h0 = __float2bfloat16(v[i].x), h1 = __float2bfloat16(v[i].y);
        __nv_bfloat16 h2 = __float2bfloat16(v[i].z), h3 = __float2bfloat16(v[i].w);
        __nv_bfloat16 l0 = __float2bfloat16(v[i].x - __bfloat162float(h0));
        __nv_bfloat16 l1 = __float2bfloat16(v[i].y - __bfloat162float(h1));
        __nv_bfloat16 l2 = __float2bfloat16(v[i].z - __bfloat162float(h2));
        __nv_bfloat16 l3 = __float2bfloat16(v[i].w - __bfloat162float(h3));
        reinterpret_cast<uint2*>(h)[base + i] = make_uint2(pk(h0, h1), pk(h2, h3));
        reinterpret_cast<uint2*>(l)[base + i] = make_uint2(pk(l0, l1), pk(l2, l3));
    }
}

// ---------------------------------------------------------------------------
// Split-bf16 GEMM on mma.sync (HMMA). All modes NT: C[M,N] = A[M,K] * B[N,K]^T
//  MODE 0/1: proj q/k (bias epilogue, writes hi/lo bf16)
//  MODE 2  : proj v   (bias epilogue, writes TRANSPOSED hi/lo bf16 via smem)
//  MODE 3  : scores   (strictly-upper tiles short-circuit to constants)
//  MODE 4  : PV       (writes fp32 output)
// CTA tile 128x128, K-chunk 32, 3-stage cp.async pipeline, row stride 80B.
// ---------------------------------------------------------------------------
#define RSTRIDE 80
#define BUFB (128 * RSTRIDE)           // 10240 per buffer
#define STAGEB (4 * BUFB)              // Ah|Al|Bh|Bl = 40960
#define SMEM_DYN (3 * STAGEB)          // 122880

template <int MODE>
__device__ __forceinline__ void stage_cp(
    uint32_t stg, const __nv_bfloat16* Ah, const __nv_bfloat16* Al,
    const __nv_bfloat16* Bh, const __nv_bfloat16* Bl,
    int m0, int n0, int k0, int tid)
{
    constexpr int LD = (MODE == 4) ? SS : DD;
    #pragma unroll
    for (int i = 0; i < 2; i++) {
        const int idx = tid + i * 256;
        const int row = idx >> 2, seg = idx & 3;
        const uint32_t d = (uint32_t)(row * RSTRIDE + seg * 16);
        const size_t ga = (size_t)(m0 + row) * LD + k0 + seg * 8;
        const size_t gb = (size_t)(n0 + row) * LD + k0 + seg * 8;
        cp16(stg + d,            Ah + ga);
        cp16(stg + BUFB + d,     Al + ga);
        cp16(stg + 2 * BUFB + d, Bh + gb);
        cp16(stg + 3 * BUFB + d, Bl + gb);
    }
}

template <int MODE>
__global__ void __launch_bounds__(256, 1) gemm5(
    const float* __restrict__ bias, const int* __restrict__ maskp,
    float* __restrict__ outF)
{
    constexpr int KDIM = (MODE == 4) ? SS : DD;
    constexpr int NCH  = KDIM / 32;
    constexpr int NOUT = (MODE == 3) ? SS : DD;

    const int tid = threadIdx.x;
    const int wid = tid >> 5, lane = tid & 31;
    const int g = lane >> 2, t4 = lane & 3;
    const int wm = wid & 1, wn = wid >> 1;          // 2 x 4 warp grid
    const int bz = blockIdx.z;
    const int m0 = blockIdx.y * 128, n0 = blockIdx.x * 128;

    // ---- scores: strictly-future tiles are mask-determined constants ----
    // |s| << ulp(1e10)/2 so fp32 s+NEG == NEG exactly; masked entries NEG+NEG.
    if (MODE == 3 && blockIdx.x > blockIdx.y) {
        const int* mrow = maskp + bz * SS;
        const int cj = (tid & 31) * 4;
        int4 mv = *reinterpret_cast<const int4*>(mrow + n0 + cj);
        float4 w;
        w.x = (mv.x == 0) ? (NEGV + NEGV) : NEGV;
        w.y = (mv.y == 0) ? (NEGV + NEGV) : NEGV;
        w.z = (mv.z == 0) ? (NEGV + NEGV) : NEGV;
        w.w = (mv.w == 0) ? (NEGV + NEGV) : NEGV;
        float* dst = g_p + (size_t)bz * SS * SS + (size_t)m0 * SS + n0;
        #pragma unroll
        for (int r = tid >> 5; r < 128; r += 8)
            *reinterpret_cast<float4*>(dst + (size_t)r * SS + cj) = w;
        return;
    }

    const __nv_bfloat16 *Ah, *Al, *Bh, *Bl;
    __nv_bfloat16 *oH = nullptr, *oL = nullptr;
    if      (MODE == 0) { Ah = g_Qh; Al = g_Ql; Bh = g_Wqh; Bl = g_Wql; oH = g_qh; oL = g_ql; }
    else if (MODE == 1) { Ah = g_Kh; Al = g_Kl; Bh = g_Wkh; Bl = g_Wkl; oH = g_kh; oL = g_kl; }
    else if (MODE == 2) { Ah = g_Vh; Al = g_Vl; Bh = g_Wvh; Bl = g_Wvl; }
    else if (MODE == 3) {
        Ah = g_qh + (size_t)bz * SS * DD; Al = g_ql + (size_t)bz * SS * DD;
        Bh = g_kh + (size_t)bz * SS * DD; Bl = g_kl + (size_t)bz * SS * DD;
    } else {
        Ah = g_ph + (size_t)bz * SS * SS; Al = g_pl + (size_t)bz * SS * SS;
        Bh = g_vth + (size_t)bz * DD * SS; Bl = g_vtl + (size_t)bz * DD * SS;
    }

    extern __shared__ char dsm[];
    const uint32_t sb = s2u(dsm);

    float c[4][4][4];
    #pragma unroll
    for (int mt = 0; mt < 4; mt++)
        #pragma unroll
        for (int nt = 0; nt < 4; nt++)
            #pragma unroll
            for (int i = 0; i < 4; i++) c[mt][nt][i] = 0.f;

    // prologue: stages 0, 1
    stage_cp<MODE>(sb,          Ah, Al, Bh, Bl, m0, n0, 0,  tid); cp_commit();
    stage_cp<MODE>(sb + STAGEB, Ah, Al, Bh, Bl, m0, n0, 32, tid); cp_commit();

    for (int ch = 0; ch < NCH; ch++) {
        if (ch + 2 < NCH)
            stage_cp<MODE>(sb + ((ch + 2) % 3) * STAGEB, Ah, Al, Bh, Bl,
                           m0, n0, (ch + 2) * 32, tid);
        cp_commit();
        cp_wait2();
        __syncthreads();

        const uint32_t stg = sb + (ch % 3) * STAGEB;
        const uint32_t sAh = stg, sAl = stg + BUFB;
        const uint32_t sBh = stg + 2 * BUFB, sBl = stg + 3 * BUFB;

        #pragma unroll
        for (int kk = 0; kk < 2; kk++) {
            const uint32_t kb = (uint32_t)(kk * 32 + t4 * 4);
            uint32_t ah[4][4], al[4][4], bh[4][2], bl[4][2];
            #pragma unroll
            for (int mt = 0; mt < 4; mt++) {
                const uint32_t r0 = (uint32_t)((wm * 64 + mt * 16 + g) * RSTRIDE) + kb;
                ah[mt][0] = ld32s(sAh + r0);
                ah[mt][1] = ld32s(sAh + r0 + 8 * RSTRIDE);
                ah[mt][2] = ld32s(sAh + r0 + 16);
                ah[mt][3] = ld32s(sAh + r0 + 8 * RSTRIDE + 16);
                al[mt][0] = ld32s(sAl + r0);
                al[mt][1] = ld32s(sAl + r0 + 8 * RSTRIDE);
                al[mt][2] = ld32s(sAl + r0 + 16);
                al[mt][3] = ld32s(sAl + r0 + 8 * RSTRIDE + 16);
            }
            #pragma unroll
            for (int nt = 0; nt < 4; nt++) {
                const uint32_t r0 = (uint32_t)((wn * 32 + nt * 8 + g) * RSTRIDE) + kb;
                bh[nt][0] = ld32s(sBh + r0);
                bh[nt][1] = ld32s(sBh + r0 + 16);
                bl[nt][0] = ld32s(sBl + r0);
                bl[nt][1] = ld32s(sBl + r0 + 16);
            }
            #pragma unroll
            for (int mt = 0; mt < 4; mt++)
                #pragma unroll
                for (int nt = 0; nt < 4; nt++) {
                    mma16816(c[mt][nt], ah[mt], bh[nt]);   // hh
                    mma16816(c[mt][nt], ah[mt], bl[nt]);   // hl
                    mma16816(c[mt][nt], al[mt], bh[nt]);   // lh
                }
        }
        __syncthreads();
    }

    // ---- epilogue ----
    if (MODE == 2) {
        // transposed write: vt[b][d][s] via smem staging (smem free post-mainloop)
        __nv_bfloat16* sm = reinterpret_cast<__nv_bfloat16*>(dsm);
        const int STR = 136;                      // bf16 units; 272B rows (16B-aligned)
        const int b = m0 >> 11, s0loc = m0 & (SS - 1);
        #pragma unroll
        for (int pass = 0; pass < 2; pass++) {
            __syncthreads();
            #pragma unroll
            for (int mt = 0; mt < 4; mt++)
                #pragma unroll
                for (int half = 0; half < 2; half++) {
                    const int rloc = wm * 64 + mt * 16 + g + half * 8;
                    #pragma unroll
                    for (int nt = 0; nt < 4; nt++) {
                        const int cloc = wn * 32 + nt * 8 + t4 * 2;
                        float v0 = c[mt][nt][half * 2]     + bias[n0 + cloc];
                        float v1 = c[mt][nt][half * 2 + 1] + bias[n0 + cloc + 1];
                        __nv_bfloat16 h0 = __float2bfloat16(v0), h1 = __float2bfloat16(v1);
                        if (pass == 0) {
                            sm[cloc * STR + rloc]       = h0;
                            sm[(cloc + 1) * STR + rloc] = h1;
                        } else {
                            sm[cloc * STR + rloc]       = __float2bfloat16(v0 - __bfloat162float(h0));
                            sm[(cloc + 1) * STR + rloc] = __float2bfloat16(v1 - __bfloat162float(h1));
                        }
                    }
                }
            __syncthreads();
            __nv_bfloat16* dstbase = (pass == 0) ? g_vth : g_vtl;
            const int ccol = tid >> 1, rh = tid & 1;
            __nv_bfloat16* dst = dstbase + ((size_t)b * DD + n0 + ccol) * SS + s0loc + rh * 64;
            const uint4* srcp = reinterpret_cast<const uint4*>(sm + ccol * STR + rh * 64);
            #pragma unroll
            for (int q8 = 0; q8 < 8; q8++)
                reinterpret_cast<uint4*>(dst)[q8] = srcp[q8];
        }
        return;
    }

    #pragma unroll
    for (int mt = 0; mt < 4; mt++) {
        #pragma unroll
        for (int half = 0; half < 2; half++) {
            const int row = m0 + wm * 64 + mt * 16 + g + half * 8;
            #pragma unroll
            for (int nt = 0; nt < 4; nt++) {
                const int cb = n0 + wn * 32 + nt * 8 + t4 * 2;
                float v0 = c[mt][nt][half * 2];
                float v1 = c[mt][nt][half * 2 + 1];
                if (MODE <= 1) {
                    v0 += bias[cb]; v1 += bias[cb + 1];
                    __nv_bfloat16 h0 = __float2bfloat16(v0), h1 = __float2bfloat16(v1);
                    __nv_bfloat16 l0 = __float2bfloat16(v0 - __bfloat162float(h0));
                    __nv_bfloat16 l1 = __float2bfloat16(v1 - __bfloat162float(h1));
                    *reinterpret_cast<uint32_t*>(oH + (size_t)row * DD + cb) = pk(h0, h1);
                    *reinterpret_cast<uint32_t*>(oL + (size_t)row * DD + cb) = pk(l0, l1);
                } else if (MODE == 3) {
                    const int* mrow = maskp + bz * SS;
                    float s0 = v0 * 0.03125f, s1 = v1 * 0.03125f;
                    if (mrow[cb] == 0)     s0 = NEGV;
                    if (mrow[cb + 1] == 0) s1 = NEGV;
                    if (cb > row)     s0 += NEGV;
                    if (cb + 1 > row) s1 += NEGV;
                    float2 st = make_float2(s0, s1);
                    *reinterpret_cast<float2*>(g_p + (size_t)bz * SS * SS +
                                               (size_t)row * SS + cb) = st;
                } else {
                    float2 st = make_float2(v0, v1);
                    *reinterpret_cast<float2*>(outF + ((size_t)bz * SS + row) * NOUT + cb) = st;
                }
            }
        }
    }
}

// ---------------------------------------------------------------------------
// Row softmax (fp32 in, split-bf16 out)
// ---------------------------------------------------------------------------
__global__ __launch_bounds__(256) void softmax_kernel() {
    const int row = blockIdx.x;
    const float* p = g_p + (size_t)row * SS;
    __nv_bfloat16* ph = g_ph + (size_t)row * SS;
    __nv_bfloat16* pl = g_pl + (size_t)row * SS;
    const int tid = threadIdx.x;

    float v[8];
    float mx = -INFINITY;
    #pragma unroll
    for (int i = 0; i < 8; i++) { v[i] = p[i * 256 + tid]; mx = fmaxf(mx, v[i]); }
    #pragma unroll
    for (int o = 16; o > 0; o >>= 1) mx = fmaxf(mx, __shfl_xor_sync(0xffffffffu, mx, o));

    __shared__ float red[8];
    if ((tid & 31) == 0) red[tid >> 5] = mx;
    __syncthreads();
    float rmax = red[0];
    #pragma unroll
    for (int i = 1; i < 8; i++) rmax = fmaxf(rmax, red[i]);

    float s = 0.f;
    #pragma unroll
    for (int i = 0; i < 8; i++) { v[i] = expf(v[i] - rmax); s += v[i]; }
    #pragma unroll
    for (int o = 16; o > 0; o >>= 1) s += __shfl_xor_sync(0xffffffffu, s, o);
    __syncthreads();
    if ((tid & 31) == 0) red[tid >> 5] = s;
    __syncthreads();
    float tot = 0.f;
    #pragma unroll
    for (int i = 0; i < 8; i++) tot += red[i];

    const float inv = 1.0f / tot;
    #pragma unroll
    for (int i = 0; i < 8; i++) {
        float w = v[i] * inv;
        __nv_bfloat16 h = __float2bfloat16(w);
        __nv_bfloat16 l = __float2bfloat16(w - __bfloat162float(h));
        ph[i * 256 + tid] = h;
        pl[i * 256 + tid] = l;
    }
}

// ---------------------------------------------------------------------------
extern "C" void kernel_launch(void* const* d_in, const int* in_sizes, int n_in,
                              void* d_out, int out_size)
{
    (void)in_sizes; (void)n_in; (void)out_size;
    const float* Q    = (const float*)d_in[0];
    const float* Kin  = (const float*)d_in[1];
    const float* Vin  = (const float*)d_in[2];
    const int*   mask = (const int*)  d_in[3];
    const float* Wq   = (const float*)d_in[4];
    const float* bq   = (const float*)d_in[5];
    const float* Wk   = (const float*)d_in[6];
    const float* bk   = (const float*)d_in[7];
    const float* Wv   = (const float*)d_in[8];
    const float* bv   = (const float*)d_in[9];
    float* out = (float*)d_out;

    cudaFuncSetAttribute(gemm5<0>, cudaFuncAttributeMaxDynamicSharedMemorySize, SMEM_DYN);
    cudaFuncSetAttribute(gemm5<1>, cudaFuncAttributeMaxDynamicSharedMemorySize, SMEM_DYN);
    cudaFuncSetAttribute(gemm5<2>, cudaFuncAttributeMaxDynamicSharedMemorySize, SMEM_DYN);
    cudaFuncSetAttribute(gemm5<3>, cudaFuncAttributeMaxDynamicSharedMemorySize, SMEM_DYN);
    cudaFuncSetAttribute(gemm5<4>, cudaFuncAttributeMaxDynamicSharedMemorySize, SMEM_DYN);

    // 1) split all inputs/weights to hi/lo bf16
    cvt_all<<<dim3(2048, 6), 256>>>(Q, Kin, Vin, Wq, Wk, Wv);
    // 2,3) q/k projections: M = 8192 (batch-flat), N = 1024
    gemm5<0><<<dim3(8, 64, 1), 256, SMEM_DYN>>>(bq, nullptr, nullptr);
    gemm5<1><<<dim3(8, 64, 1), 256, SMEM_DYN>>>(bk, nullptr, nullptr);
    // 4) scores (4th launch -> profiled): per-batch 2048x2048, K = 1024
    gemm5<3><<<dim3(16, 16, NB), 256, SMEM_DYN>>>(nullptr, mask, nullptr);
    // 5) v projection (writes transposed)
    gemm5<2><<<dim3(8, 64, 1), 256, SMEM_DYN>>>(bv, nullptr, nullptr);
    // 6) softmax
    softmax_kernel<<<NB * SS, 256>>>();
    // 7) O = P @ V : per-batch 2048 x 1024, K = 2048
    gemm5<4><<<dim3(8, 16, NB), 256, SMEM_DYN>>>(nullptr, nullptr, out);
}

// round 6
// speedup vs baseline: 1.4482x; 1.4482x over previous
#include <cuda_runtime.h>
#include <cuda_bf16.h>
#include <cstdint>
#include <math.h>

#define NB 4
#define SS 2048
#define DD 1024
#define NEGV (-1e10f)

// ---------------------------------------------------------------------------
// Device-global scratch (allocation-free per harness rules)
// ---------------------------------------------------------------------------
__device__ __align__(128) __nv_bfloat16 g_Qh[NB*SS*DD], g_Ql[NB*SS*DD];
__device__ __align__(128) __nv_bfloat16 g_Kh[NB*SS*DD], g_Kl[NB*SS*DD];
__device__ __align__(128) __nv_bfloat16 g_Vh[NB*SS*DD], g_Vl[NB*SS*DD];
__device__ __align__(128) __nv_bfloat16 g_Wqh[DD*DD], g_Wql[DD*DD];
__device__ __align__(128) __nv_bfloat16 g_Wkh[DD*DD], g_Wkl[DD*DD];
__device__ __align__(128) __nv_bfloat16 g_Wvh[DD*DD], g_Wvl[DD*DD];
__device__ __align__(128) __nv_bfloat16 g_qh[NB*SS*DD], g_ql[NB*SS*DD];
__device__ __align__(128) __nv_bfloat16 g_kh[NB*SS*DD], g_kl[NB*SS*DD];
__device__ __align__(128) __nv_bfloat16 g_vh[NB*SS*DD], g_vl[NB*SS*DD];
__device__ __align__(128) __nv_bfloat16 g_vth[NB*DD*SS], g_vtl[NB*DD*SS]; // [b][d][s]
__device__ float         g_p[(size_t)NB*SS*SS];                           // fp32 scores
__device__ __align__(128) __nv_bfloat16 g_ph[(size_t)NB*SS*SS], g_pl[(size_t)NB*SS*SS];

// ---------------------------------------------------------------------------
// helpers
// ---------------------------------------------------------------------------
__device__ __forceinline__ uint32_t s2u(const void* p) {
    return (uint32_t)__cvta_generic_to_shared(p);
}
__device__ __forceinline__ void cp16(uint32_t dst, const void* src) {
    asm volatile("cp.async.cg.shared.global [%0], [%1], 16;\n"
                 :: "r"(dst), "l"(src) : "memory");
}
__device__ __forceinline__ void cp_commit() {
    asm volatile("cp.async.commit_group;\n" ::: "memory");
}
__device__ __forceinline__ void cp_wait2() {
    asm volatile("cp.async.wait_group 2;\n" ::: "memory");
}
__device__ __forceinline__ uint32_t ld32s(uint32_t a) {
    uint32_t v;
    asm volatile("ld.shared.b32 %0, [%1];" : "=r"(v) : "r"(a));
    return v;
}
__device__ __forceinline__ void mma16816(float* c, const uint32_t* a, const uint32_t* b) {
    asm volatile("mma.sync.aligned.m16n8k16.row.col.f32.bf16.bf16.f32 "
        "{%0,%1,%2,%3}, {%4,%5,%6,%7}, {%8,%9}, {%0,%1,%2,%3};"
        : "+f"(c[0]), "+f"(c[1]), "+f"(c[2]), "+f"(c[3])
        : "r"(a[0]), "r"(a[1]), "r"(a[2]), "r"(a[3]), "r"(b[0]), "r"(b[1]));
}
__device__ __forceinline__ uint32_t pk(__nv_bfloat16 a, __nv_bfloat16 b) {
    __nv_bfloat162 t(a, b);
    return *reinterpret_cast<uint32_t*>(&t);
}

// ---------------------------------------------------------------------------
// One-shot fp32 -> (bf16 hi, bf16 lo) split for all 6 tensors (MLP=4).
// ---------------------------------------------------------------------------
__global__ __launch_bounds__(256) void cvt_all(
    const float* __restrict__ Q, const float* __restrict__ K,
    const float* __restrict__ V, const float* __restrict__ Wq,
    const float* __restrict__ Wk, const float* __restrict__ Wv)
{
    const int seg = blockIdx.y;
    const float* src; __nv_bfloat16 *h, *l; int n4;
    if      (seg == 0) { src = Q;  h = g_Qh;  l = g_Ql;  n4 = NB*SS*DD/4; }
    else if (seg == 1) { src = K;  h = g_Kh;  l = g_Kl;  n4 = NB*SS*DD/4; }
    else if (seg == 2) { src = V;  h = g_Vh;  l = g_Vl;  n4 = NB*SS*DD/4; }
    else if (seg == 3) { src = Wq; h = g_Wqh; l = g_Wql; n4 = DD*DD/4; }
    else if (seg == 4) { src = Wk; h = g_Wkh; l = g_Wkl; n4 = DD*DD/4; }
    else               { src = Wv; h = g_Wvh; l = g_Wvl; n4 = DD*DD/4; }

    const int base = (blockIdx.x * 256 + threadIdx.x) * 4;
    if (base >= n4) return;
    float4 v[4];
    #pragma unroll
    for (int i = 0; i < 4; i++) v[i] = reinterpret_cast<const float4*>(src)[base + i];
    #pragma unroll
    for (int i = 0; i < 4; i++) {
        __nv_bfloat16 h0 = __float2bfloat16(v[i].x), h1 = __float2bfloat16(v[i].y);
        __nv_bfloat16 h2 = __float2bfloat16(v[i].z), h3 = __float2bfloat16(v[i].w);
        __nv_bfloat16 l0 = __float2bfloat16(v[i].x - __bfloat162float(h0));
        __nv_bfloat16 l1 = __float2bfloat16(v[i].y - __bfloat162float(h1));
        __nv_bfloat16 l2 = __float2bfloat16(v[i].z - __bfloat162float(h2));
        __nv_bfloat16 l3 = __float2bfloat16(v[i].w - __bfloat162float(h3));
        reinterpret_cast<uint2*>(h)[base + i] = make_uint2(pk(h0, h1), pk(h2, h3));
        reinterpret_cast<uint2*>(l)[base + i] = make_uint2(pk(l0, l1), pk(l2, l3));
    }
}

// ---------------------------------------------------------------------------
// v [b][s][d] -> vt [b][d][s] (hi and lo)
// ---------------------------------------------------------------------------
__global__ __launch_bounds__(256) void transpose_v() {
    __shared__ __nv_bfloat16 t[64][65];
    const int b = blockIdx.z, d0 = blockIdx.x * 64, s0 = blockIdx.y * 64;
    const int tid = threadIdx.x;
    const __nv_bfloat16* srcs[2] = { g_vh, g_vl };
    __nv_bfloat16*       dsts[2] = { g_vth, g_vtl };
    for (int p = 0; p < 2; p++) {
        const __nv_bfloat16* src = srcs[p];
        __nv_bfloat16* dst = dsts[p];
        for (int i = tid; i < 64 * 64; i += 256) {
            int r = i >> 6, c = i & 63;
            t[r][c] = src[((size_t)b * SS + s0 + r) * DD + d0 + c];
        }
        __syncthreads();
        for (int i = tid; i < 64 * 64; i += 256) {
            int r = i >> 6, c = i & 63;
            dst[((size_t)b * DD + d0 + r) * SS + s0 + c] = t[c][r];
        }
        __syncthreads();
    }
}

// ---------------------------------------------------------------------------
// Split-bf16 GEMM on mma.sync (HMMA). All modes NT: C[M,N] = A[M,K] * B[N,K]^T
//  MODE 0/1/2: proj q/k/v (bias epilogue, writes hi/lo bf16)
//  MODE 3    : scores (strictly-upper tiles short-circuit; scale+mask epilogue)
//  MODE 4    : PV (writes fp32 output)
// CTA tile 128x128, 512 threads (4x4 warps, 32x32 warp tile), K-chunk 32,
// 3-stage cp.async pipeline, row stride 80B.
// ---------------------------------------------------------------------------
#define RSTRIDE 80
#define BUFB (128 * RSTRIDE)           // 10240 per buffer
#define STAGEB (4 * BUFB)              // Ah|Al|Bh|Bl = 40960
#define SMEM_DYN (3 * STAGEB)          // 122880

template <int MODE>
__device__ __forceinline__ void stage_cp(
    uint32_t stg, const __nv_bfloat16* Ah, const __nv_bfloat16* Al,
    const __nv_bfloat16* Bh, const __nv_bfloat16* Bl,
    int m0, int n0, int k0, int tid)
{
    constexpr int LD = (MODE == 4) ? SS : DD;
    const int row = tid >> 2, seg = tid & 3;            // 512 threads: 128 rows x 4 segs
    const uint32_t d = (uint32_t)(row * RSTRIDE + seg * 16);
    const size_t ga = (size_t)(m0 + row) * LD + k0 + seg * 8;
    const size_t gb = (size_t)(n0 + row) * LD + k0 + seg * 8;
    cp16(stg + d,            Ah + ga);
    cp16(stg + BUFB + d,     Al + ga);
    cp16(stg + 2 * BUFB + d, Bh + gb);
    cp16(stg + 3 * BUFB + d, Bl + gb);
}

template <int MODE>
__global__ void __launch_bounds__(512, 1) gemm5(
    const float* __restrict__ bias, const int* __restrict__ maskp,
    float* __restrict__ outF)
{
    constexpr int KDIM = (MODE == 4) ? SS : DD;
    constexpr int NCH  = KDIM / 32;
    constexpr int NOUT = (MODE == 3) ? SS : DD;

    const int tid = threadIdx.x;
    const int wid = tid >> 5, lane = tid & 31;
    const int g = lane >> 2, t4 = lane & 3;
    const int wm = wid & 3, wn = wid >> 2;          // 4 x 4 warp grid, 32x32 warp tile
    const int bz = blockIdx.z;
    const int m0 = blockIdx.y * 128, n0 = blockIdx.x * 128;

    // ---- scores: strictly-future tiles are mask-determined constants ----
    // |s| << ulp(1e10)/2 so fp32 s+NEG == NEG exactly; masked entries NEG+NEG.
    if (MODE == 3 && blockIdx.x > blockIdx.y) {
        const int* mrow = maskp + bz * SS;
        const int cj = (tid & 31) * 4;
        int4 mv = *reinterpret_cast<const int4*>(mrow + n0 + cj);
        float4 w;
        w.x = (mv.x == 0) ? (NEGV + NEGV) : NEGV;
        w.y = (mv.y == 0) ? (NEGV + NEGV) : NEGV;
        w.z = (mv.z == 0) ? (NEGV + NEGV) : NEGV;
        w.w = (mv.w == 0) ? (NEGV + NEGV) : NEGV;
        float* dst = g_p + (size_t)bz * SS * SS + (size_t)m0 * SS + n0;
        #pragma unroll
        for (int r = tid >> 5; r < 128; r += 16)
            *reinterpret_cast<float4*>(dst + (size_t)r * SS + cj) = w;
        return;
    }

    const __nv_bfloat16 *Ah, *Al, *Bh, *Bl;
    __nv_bfloat16 *oH = nullptr, *oL = nullptr;
    if      (MODE == 0) { Ah = g_Qh; Al = g_Ql; Bh = g_Wqh; Bl = g_Wql; oH = g_qh; oL = g_ql; }
    else if (MODE == 1) { Ah = g_Kh; Al = g_Kl; Bh = g_Wkh; Bl = g_Wkl; oH = g_kh; oL = g_kl; }
    else if (MODE == 2) { Ah = g_Vh; Al = g_Vl; Bh = g_Wvh; Bl = g_Wvl; oH = g_vh; oL = g_vl; }
    else if (MODE == 3) {
        Ah = g_qh + (size_t)bz * SS * DD; Al = g_ql + (size_t)bz * SS * DD;
        Bh = g_kh + (size_t)bz * SS * DD; Bl = g_kl + (size_t)bz * SS * DD;
    } else {
        Ah = g_ph + (size_t)bz * SS * SS; Al = g_pl + (size_t)bz * SS * SS;
        Bh = g_vth + (size_t)bz * DD * SS; Bl = g_vtl + (size_t)bz * DD * SS;
    }

    extern __shared__ char dsm[];
    const uint32_t sb = s2u(dsm);

    float c[2][4][4];
    #pragma unroll
    for (int mt = 0; mt < 2; mt++)
        #pragma unroll
        for (int nt = 0; nt < 4; nt++)
            #pragma unroll
            for (int i = 0; i < 4; i++) c[mt][nt][i] = 0.f;

    // prologue: stages 0, 1
    stage_cp<MODE>(sb,          Ah, Al, Bh, Bl, m0, n0, 0,  tid); cp_commit();
    stage_cp<MODE>(sb + STAGEB, Ah, Al, Bh, Bl, m0, n0, 32, tid); cp_commit();

    for (int ch = 0; ch < NCH; ch++) {
        if (ch + 2 < NCH)
            stage_cp<MODE>(sb + ((ch + 2) % 3) * STAGEB, Ah, Al, Bh, Bl,
                           m0, n0, (ch + 2) * 32, tid);
        cp_commit();
        cp_wait2();
        __syncthreads();

        const uint32_t stg = sb + (ch % 3) * STAGEB;
        const uint32_t sAh = stg, sAl = stg + BUFB;
        const uint32_t sBh = stg + 2 * BUFB, sBl = stg + 3 * BUFB;

        #pragma unroll
        for (int kk = 0; kk < 2; kk++) {
            const uint32_t kb = (uint32_t)(kk * 32 + t4 * 4);
            uint32_t ah[2][4], al[2][4], bh[4][2], bl[4][2];
            #pragma unroll
            for (int mt = 0; mt < 2; mt++) {
                const uint32_t r0 = (uint32_t)((wm * 32 + mt * 16 + g) * RSTRIDE) + kb;
                ah[mt][0] = ld32s(sAh + r0);
                ah[mt][1] = ld32s(sAh + r0 + 8 * RSTRIDE);
                ah[mt][2] = ld32s(sAh + r0 + 16);
                ah[mt][3] = ld32s(sAh + r0 + 8 * RSTRIDE + 16);
                al[mt][0] = ld32s(sAl + r0);
                al[mt][1] = ld32s(sAl + r0 + 8 * RSTRIDE);
                al[mt][2] = ld32s(sAl + r0 + 16);
                al[mt][3] = ld32s(sAl + r0 + 8 * RSTRIDE + 16);
            }
            #pragma unroll
            for (int nt = 0; nt < 4; nt++) {
                const uint32_t r0 = (uint32_t)((wn * 32 + nt * 8 + g) * RSTRIDE) + kb;
                bh[nt][0] = ld32s(sBh + r0);
                bh[nt][1] = ld32s(sBh + r0 + 16);
                bl[nt][0] = ld32s(sBl + r0);
                bl[nt][1] = ld32s(sBl + r0 + 16);
            }
            #pragma unroll
            for (int mt = 0; mt < 2; mt++)
                #pragma unroll
                for (int nt = 0; nt < 4; nt++) {
                    mma16816(c[mt][nt], ah[mt], bh[nt]);   // hh
                    mma16816(c[mt][nt], ah[mt], bl[nt]);   // hl
                    mma16816(c[mt][nt], al[mt], bh[nt]);   // lh
                }
        }
        __syncthreads();
    }

    // ---- epilogue ----
    #pragma unroll
    for (int mt = 0; mt < 2; mt++) {
        #pragma unroll
        for (int half = 0; half < 2; half++) {
            const int row = m0 + wm * 32 + mt * 16 + g + half * 8;
            #pragma unroll
            for (int nt = 0; nt < 4; nt++) {
                const int cb = n0 + wn * 32 + nt * 8 + t4 * 2;
                float v0 = c[mt][nt][half * 2];
                float v1 = c[mt][nt][half * 2 + 1];
                if (MODE <= 2) {
                    v0 += bias[cb]; v1 += bias[cb + 1];
                    __nv_bfloat16 h0 = __float2bfloat16(v0), h1 = __float2bfloat16(v1);
                    __nv_bfloat16 l0 = __float2bfloat16(v0 - __bfloat162float(h0));
                    __nv_bfloat16 l1 = __float2bfloat16(v1 - __bfloat162float(h1));
                    *reinterpret_cast<uint32_t*>(oH + (size_t)row * DD + cb) = pk(h0, h1);
                    *reinterpret_cast<uint32_t*>(oL + (size_t)row * DD + cb) = pk(l0, l1);
                } else if (MODE == 3) {
                    const int* mrow = maskp + bz * SS;
                    float s0 = v0 * 0.03125f, s1 = v1 * 0.03125f;
                    if (mrow[cb] == 0)     s0 = NEGV;
                    if (mrow[cb + 1] == 0) s1 = NEGV;
                    if (cb > row)     s0 += NEGV;
                    if (cb + 1 > row) s1 += NEGV;
                    float2 st = make_float2(s0, s1);
                    *reinterpret_cast<float2*>(g_p + (size_t)bz * SS * SS +
                                               (size_t)row * SS + cb) = st;
                } else {
                    float2 st = make_float2(v0, v1);
                    *reinterpret_cast<float2*>(outF + ((size_t)bz * SS + row) * NOUT + cb) = st;
                }
            }
        }
    }
}

// ---------------------------------------------------------------------------
// Row softmax (fp32 in, split-bf16 out)
// ---------------------------------------------------------------------------
__global__ __launch_bounds__(256) void softmax_kernel() {
    const int row = blockIdx.x;
    const float* p = g_p + (size_t)row * SS;
    __nv_bfloat16* ph = g_ph + (size_t)row * SS;
    __nv_bfloat16* pl = g_pl + (size_t)row * SS;
    const int tid = threadIdx.x;

    float v[8];
    float mx = -INFINITY;
    #pragma unroll
    for (int i = 0; i < 8; i++) { v[i] = p[i * 256 + tid]; mx = fmaxf(mx, v[i]); }
    #pragma unroll
    for (int o = 16; o > 0; o >>= 1) mx = fmaxf(mx, __shfl_xor_sync(0xffffffffu, mx, o));

    __shared__ float red[8];
    if ((tid & 31) == 0) red[tid >> 5] = mx;
    __syncthreads();
    float rmax = red[0];
    #pragma unroll
    for (int i = 1; i < 8; i++) rmax = fmaxf(rmax, red[i]);

    float s = 0.f;
    #pragma unroll
    for (int i = 0; i < 8; i++) { v[i] = expf(v[i] - rmax); s += v[i]; }
    #pragma unroll
    for (int o = 16; o > 0; o >>= 1) s += __shfl_xor_sync(0xffffffffu, s, o);
    __syncthreads();
    if ((tid & 31) == 0) red[tid >> 5] = s;
    __syncthreads();
    float tot = 0.f;
    #pragma unroll
    for (int i = 0; i < 8; i++) tot += red[i];

    const float inv = 1.0f / tot;
    #pragma unroll
    for (int i = 0; i < 8; i++) {
        float w = v[i] * inv;
        __nv_bfloat16 h = __float2bfloat16(w);
        __nv_bfloat16 l = __float2bfloat16(w - __bfloat162float(h));
        ph[i * 256 + tid] = h;
        pl[i * 256 + tid] = l;
    }
}

// ---------------------------------------------------------------------------
extern "C" void kernel_launch(void* const* d_in, const int* in_sizes, int n_in,
                              void* d_out, int out_size)
{
    (void)in_sizes; (void)n_in; (void)out_size;
    const float* Q    = (const float*)d_in[0];
    const float* Kin  = (const float*)d_in[1];
    const float* Vin  = (const float*)d_in[2];
    const int*   mask = (const int*)  d_in[3];
    const float* Wq   = (const float*)d_in[4];
    const float* bq   = (const float*)d_in[5];
    const float* Wk   = (const float*)d_in[6];
    const float* bk   = (const float*)d_in[7];
    const float* Wv   = (const float*)d_in[8];
    const float* bv   = (const float*)d_in[9];
    float* out = (float*)d_out;

    cudaFuncSetAttribute(gemm5<0>, cudaFuncAttributeMaxDynamicSharedMemorySize, SMEM_DYN);
    cudaFuncSetAttribute(gemm5<1>, cudaFuncAttributeMaxDynamicSharedMemorySize, SMEM_DYN);
    cudaFuncSetAttribute(gemm5<2>, cudaFuncAttributeMaxDynamicSharedMemorySize, SMEM_DYN);
    cudaFuncSetAttribute(gemm5<3>, cudaFuncAttributeMaxDynamicSharedMemorySize, SMEM_DYN);
    cudaFuncSetAttribute(gemm5<4>, cudaFuncAttributeMaxDynamicSharedMemorySize, SMEM_DYN);

    // 1) split all inputs/weights to hi/lo bf16
    cvt_all<<<dim3(2048, 6), 256>>>(Q, Kin, Vin, Wq, Wk, Wv);
    // 2,3) q/k projections: M = 8192 (batch-flat), N = 1024
    gemm5<0><<<dim3(8, 64, 1), 512, SMEM_DYN>>>(bq, nullptr, nullptr);
    gemm5<1><<<dim3(8, 64, 1), 512, SMEM_DYN>>>(bk, nullptr, nullptr);
    // 4) scores (4th launch -> profiled): per-batch 2048x2048, K = 1024
    gemm5<3><<<dim3(16, 16, NB), 512, SMEM_DYN>>>(nullptr, mask, nullptr);
    // 5) v projection
    gemm5<2><<<dim3(8, 64, 1), 512, SMEM_DYN>>>(bv, nullptr, nullptr);
    // 6) v transpose
    transpose_v<<<dim3(16, 32, NB), 256>>>();
    // 7) softmax
    softmax_kernel<<<NB * SS, 256>>>();
    // 8) O = P @ V : per-batch 2048 x 1024, K = 2048
    gemm5<4><<<dim3(8, 16, NB), 512, SMEM_DYN>>>(nullptr, nullptr, out);
}

// round 7
// speedup vs baseline: 1.6279x; 1.1241x over previous
#include <cuda_runtime.h>
#include <cuda_bf16.h>
#include <cstdint>
#include <math.h>

#define NB 4
#define SS 2048
#define DD 1024
#define NEGV (-1e10f)

// ---------------------------------------------------------------------------
// Device-global scratch (allocation-free per harness rules)
// ---------------------------------------------------------------------------
__device__ __align__(128) __nv_bfloat16 g_Qh[NB*SS*DD], g_Ql[NB*SS*DD];
__device__ __align__(128) __nv_bfloat16 g_Kh[NB*SS*DD], g_Kl[NB*SS*DD];
__device__ __align__(128) __nv_bfloat16 g_Vh[NB*SS*DD], g_Vl[NB*SS*DD];
__device__ __align__(128) __nv_bfloat16 g_Wqh[DD*DD], g_Wql[DD*DD];
__device__ __align__(128) __nv_bfloat16 g_Wkh[DD*DD], g_Wkl[DD*DD];
__device__ __align__(128) __nv_bfloat16 g_Wvh[DD*DD], g_Wvl[DD*DD];
__device__ __align__(128) __nv_bfloat16 g_qh[NB*SS*DD], g_ql[NB*SS*DD];
__device__ __align__(128) __nv_bfloat16 g_kh[NB*SS*DD], g_kl[NB*SS*DD];
__device__ __align__(128) __nv_bfloat16 g_vh[NB*SS*DD], g_vl[NB*SS*DD];
__device__ __align__(128) __nv_bfloat16 g_vth[NB*DD*SS], g_vtl[NB*DD*SS]; // [b][d][s]
__device__ float         g_p[(size_t)NB*SS*SS];                           // fp32 scores
__device__ __align__(128) __nv_bfloat16 g_ph[(size_t)NB*SS*SS], g_pl[(size_t)NB*SS*SS];
__device__ int           g_deg[NB*SS];      // per-row degenerate-softmax flag

// ---------------------------------------------------------------------------
// helpers
// ---------------------------------------------------------------------------
__device__ __forceinline__ uint32_t s2u(const void* p) {
    return (uint32_t)__cvta_generic_to_shared(p);
}
__device__ __forceinline__ void cp16(uint32_t dst, const void* src) {
    asm volatile("cp.async.cg.shared.global [%0], [%1], 16;\n"
                 :: "r"(dst), "l"(src) : "memory");
}
__device__ __forceinline__ void cp_commit() {
    asm volatile("cp.async.commit_group;\n" ::: "memory");
}
__device__ __forceinline__ void cp_wait2() {
    asm volatile("cp.async.wait_group 2;\n" ::: "memory");
}
__device__ __forceinline__ uint32_t ld32s(uint32_t a) {
    uint32_t v;
    asm volatile("ld.shared.b32 %0, [%1];" : "=r"(v) : "r"(a));
    return v;
}
__device__ __forceinline__ void mma16816(float* c, const uint32_t* a, const uint32_t* b) {
    asm volatile("mma.sync.aligned.m16n8k16.row.col.f32.bf16.bf16.f32 "
        "{%0,%1,%2,%3}, {%4,%5,%6,%7}, {%8,%9}, {%0,%1,%2,%3};"
        : "+f"(c[0]), "+f"(c[1]), "+f"(c[2]), "+f"(c[3])
        : "r"(a[0]), "r"(a[1]), "r"(a[2]), "r"(a[3]), "r"(b[0]), "r"(b[1]));
}
__device__ __forceinline__ uint32_t pk(__nv_bfloat16 a, __nv_bfloat16 b) {
    __nv_bfloat162 t(a, b);
    return *reinterpret_cast<uint32_t*>(&t);
}

// ---------------------------------------------------------------------------
// One-shot fp32 -> (bf16 hi, bf16 lo) split for all 6 tensors (MLP=4).
// ---------------------------------------------------------------------------
__global__ __launch_bounds__(256) void cvt_all(
    const float* __restrict__ Q, const float* __restrict__ K,
    const float* __restrict__ V, const float* __restrict__ Wq,
    const float* __restrict__ Wk, const float* __restrict__ Wv)
{
    const int seg = blockIdx.y;
    const float* src; __nv_bfloat16 *h, *l; int n4;
    if      (seg == 0) { src = Q;  h = g_Qh;  l = g_Ql;  n4 = NB*SS*DD/4; }
    else if (seg == 1) { src = K;  h = g_Kh;  l = g_Kl;  n4 = NB*SS*DD/4; }
    else if (seg == 2) { src = V;  h = g_Vh;  l = g_Vl;  n4 = NB*SS*DD/4; }
    else if (seg == 3) { src = Wq; h = g_Wqh; l = g_Wql; n4 = DD*DD/4; }
    else if (seg == 4) { src = Wk; h = g_Wkh; l = g_Wkl; n4 = DD*DD/4; }
    else               { src = Wv; h = g_Wvh; l = g_Wvl; n4 = DD*DD/4; }

    const int base = (blockIdx.x * 256 + threadIdx.x) * 4;
    if (base >= n4) return;
    float4 v[4];
    #pragma unroll
    for (int i = 0; i < 4; i++) v[i] = reinterpret_cast<const float4*>(src)[base + i];
    #pragma unroll
    for (int i = 0; i < 4; i++) {
        __nv_bfloat16 h0 = __float2bfloat16(v[i].x), h1 = __float2bfloat16(v[i].y);
        __nv_bfloat16 h2 = __float2bfloat16(v[i].z), h3 = __float2bfloat16(v[i].w);
        __nv_bfloat16 l0 = __float2bfloat16(v[i].x - __bfloat162float(h0));
        __nv_bfloat16 l1 = __float2bfloat16(v[i].y - __bfloat162float(h1));
        __nv_bfloat16 l2 = __float2bfloat16(v[i].z - __bfloat162float(h2));
        __nv_bfloat16 l3 = __float2bfloat16(v[i].w - __bfloat162float(h3));
        reinterpret_cast<uint2*>(h)[base + i] = make_uint2(pk(h0, h1), pk(h2, h3));
        reinterpret_cast<uint2*>(l)[base + i] = make_uint2(pk(l0, l1), pk(l2, l3));
    }
}

// ---------------------------------------------------------------------------
// v [b][s][d] -> vt [b][d][s] (hi and lo)
// ---------------------------------------------------------------------------
__global__ __launch_bounds__(256) void transpose_v() {
    __shared__ __nv_bfloat16 t[64][65];
    const int b = blockIdx.z, d0 = blockIdx.x * 64, s0 = blockIdx.y * 64;
    const int tid = threadIdx.x;
    const __nv_bfloat16* srcs[2] = { g_vh, g_vl };
    __nv_bfloat16*       dsts[2] = { g_vth, g_vtl };
    for (int p = 0; p < 2; p++) {
        const __nv_bfloat16* src = srcs[p];
        __nv_bfloat16* dst = dsts[p];
        for (int i = tid; i < 64 * 64; i += 256) {
            int r = i >> 6, c = i & 63;
            t[r][c] = src[((size_t)b * SS + s0 + r) * DD + d0 + c];
        }
        __syncthreads();
        for (int i = tid; i < 64 * 64; i += 256) {
            int r = i >> 6, c = i & 63;
            dst[((size_t)b * DD + d0 + r) * SS + s0 + c] = t[c][r];
        }
        __syncthreads();
    }
}

// ---------------------------------------------------------------------------
// Split-bf16 GEMM on mma.sync (HMMA). All modes NT: C[M,N] = A[M,K] * B[N,K]^T
//  MODE 0/1/2: proj q/k/v (bias epilogue, writes hi/lo bf16)
//  MODE 3    : scores (strictly-upper tiles skipped entirely)
//  MODE 4    : PV (causal K-limit via degeneracy flags; writes fp32 output)
// CTA tile 128x128, 512 threads (4x4 warps, 32x32 warp tile), K-chunk 32,
// 3-stage cp.async pipeline, row stride 80B.
// ---------------------------------------------------------------------------
#define RSTRIDE 80
#define BUFB (128 * RSTRIDE)           // 10240 per buffer
#define STAGEB (4 * BUFB)              // Ah|Al|Bh|Bl = 40960
#define SMEM_DYN (3 * STAGEB)          // 122880

template <int MODE>
__device__ __forceinline__ void stage_cp(
    uint32_t stg, const __nv_bfloat16* Ah, const __nv_bfloat16* Al,
    const __nv_bfloat16* Bh, const __nv_bfloat16* Bl,
    int m0, int n0, int k0, int tid)
{
    constexpr int LD = (MODE == 4) ? SS : DD;
    const int row = tid >> 2, seg = tid & 3;            // 512 threads: 128 rows x 4 segs
    const uint32_t d = (uint32_t)(row * RSTRIDE + seg * 16);
    const size_t ga = (size_t)(m0 + row) * LD + k0 + seg * 8;
    const size_t gb = (size_t)(n0 + row) * LD + k0 + seg * 8;
    cp16(stg + d,            Ah + ga);
    cp16(stg + BUFB + d,     Al + ga);
    cp16(stg + 2 * BUFB + d, Bh + gb);
    cp16(stg + 3 * BUFB + d, Bl + gb);
}

template <int MODE>
__global__ void __launch_bounds__(512, 1) gemm5(
    const float* __restrict__ bias, const int* __restrict__ maskp,
    float* __restrict__ outF)
{
    constexpr int KDIM = (MODE == 4) ? SS : DD;
    constexpr int NOUT = (MODE == 3) ? SS : DD;

    const int tid = threadIdx.x;
    const int wid = tid >> 5, lane = tid & 31;
    const int g = lane >> 2, t4 = lane & 3;
    const int wm = wid & 3, wn = wid >> 2;          // 4 x 4 warp grid, 32x32 warp tile
    const int bz = blockIdx.z;
    const int m0 = blockIdx.y * 128, n0 = blockIdx.x * 128;

    // ---- scores: strictly-future tiles are never read downstream ----
    if (MODE == 3 && blockIdx.x > blockIdx.y) return;

    // ---- PV: causal K-limit unless a degenerate row is present ----
    int nch = KDIM / 32;
    if (MODE == 4) {
        __shared__ int s_any;
        if (tid == 0) s_any = 0;
        __syncthreads();
        if (tid < 128 && g_deg[bz * SS + m0 + tid]) s_any = 1;
        __syncthreads();
        if (!s_any) nch = (m0 >> 5) + 4;     // K up to m0+128 only
    }

    const __nv_bfloat16 *Ah, *Al, *Bh, *Bl;
    __nv_bfloat16 *oH = nullptr, *oL = nullptr;
    if      (MODE == 0) { Ah = g_Qh; Al = g_Ql; Bh = g_Wqh; Bl = g_Wql; oH = g_qh; oL = g_ql; }
    else if (MODE == 1) { Ah = g_Kh; Al = g_Kl; Bh = g_Wkh; Bl = g_Wkl; oH = g_kh; oL = g_kl; }
    else if (MODE == 2) { Ah = g_Vh; Al = g_Vl; Bh = g_Wvh; Bl = g_Wvl; oH = g_vh; oL = g_vl; }
    else if (MODE == 3) {
        Ah = g_qh + (size_t)bz * SS * DD; Al = g_ql + (size_t)bz * SS * DD;
        Bh = g_kh + (size_t)bz * SS * DD; Bl = g_kl + (size_t)bz * SS * DD;
    } else {
        Ah = g_ph + (size_t)bz * SS * SS; Al = g_pl + (size_t)bz * SS * SS;
        Bh = g_vth + (size_t)bz * DD * SS; Bl = g_vtl + (size_t)bz * DD * SS;
    }

    extern __shared__ char dsm[];
    const uint32_t sb = s2u(dsm);

    float c[2][4][4];
    #pragma unroll
    for (int mt = 0; mt < 2; mt++)
        #pragma unroll
        for (int nt = 0; nt < 4; nt++)
            #pragma unroll
            for (int i = 0; i < 4; i++) c[mt][nt][i] = 0.f;

    // prologue: stages 0, 1  (nch >= 4 always)
    stage_cp<MODE>(sb,          Ah, Al, Bh, Bl, m0, n0, 0,  tid); cp_commit();
    stage_cp<MODE>(sb + STAGEB, Ah, Al, Bh, Bl, m0, n0, 32, tid); cp_commit();

    for (int ch = 0; ch < nch; ch++) {
        if (ch + 2 < nch)
            stage_cp<MODE>(sb + ((ch + 2) % 3) * STAGEB, Ah, Al, Bh, Bl,
                           m0, n0, (ch + 2) * 32, tid);
        cp_commit();
        cp_wait2();
        __syncthreads();

        const uint32_t stg = sb + (ch % 3) * STAGEB;
        const uint32_t sAh = stg, sAl = stg + BUFB;
        const uint32_t sBh = stg + 2 * BUFB, sBl = stg + 3 * BUFB;

        #pragma unroll
        for (int kk = 0; kk < 2; kk++) {
            const uint32_t kb = (uint32_t)(kk * 32 + t4 * 4);
            uint32_t ah[2][4], al[2][4], bh[4][2], bl[4][2];
            #pragma unroll
            for (int mt = 0; mt < 2; mt++) {
                const uint32_t r0 = (uint32_t)((wm * 32 + mt * 16 + g) * RSTRIDE) + kb;
                ah[mt][0] = ld32s(sAh + r0);
                ah[mt][1] = ld32s(sAh + r0 + 8 * RSTRIDE);
                ah[mt][2] = ld32s(sAh + r0 + 16);
                ah[mt][3] = ld32s(sAh + r0 + 8 * RSTRIDE + 16);
                al[mt][0] = ld32s(sAl + r0);
                al[mt][1] = ld32s(sAl + r0 + 8 * RSTRIDE);
                al[mt][2] = ld32s(sAl + r0 + 16);
                al[mt][3] = ld32s(sAl + r0 + 8 * RSTRIDE + 16);
            }
            #pragma unroll
            for (int nt = 0; nt < 4; nt++) {
                const uint32_t r0 = (uint32_t)((wn * 32 + nt * 8 + g) * RSTRIDE) + kb;
                bh[nt][0] = ld32s(sBh + r0);
                bh[nt][1] = ld32s(sBh + r0 + 16);
                bl[nt][0] = ld32s(sBl + r0);
                bl[nt][1] = ld32s(sBl + r0 + 16);
            }
            #pragma unroll
            for (int mt = 0; mt < 2; mt++)
                #pragma unroll
                for (int nt = 0; nt < 4; nt++) {
                    mma16816(c[mt][nt], ah[mt], bh[nt]);   // hh
                    mma16816(c[mt][nt], ah[mt], bl[nt]);   // hl
                    mma16816(c[mt][nt], al[mt], bh[nt]);   // lh
                }
        }
        __syncthreads();
    }

    // ---- epilogue ----
    #pragma unroll
    for (int mt = 0; mt < 2; mt++) {
        #pragma unroll
        for (int half = 0; half < 2; half++) {
            const int row = m0 + wm * 32 + mt * 16 + g + half * 8;
            #pragma unroll
            for (int nt = 0; nt < 4; nt++) {
                const int cb = n0 + wn * 32 + nt * 8 + t4 * 2;
                float v0 = c[mt][nt][half * 2];
                float v1 = c[mt][nt][half * 2 + 1];
                if (MODE <= 2) {
                    v0 += bias[cb]; v1 += bias[cb + 1];
                    __nv_bfloat16 h0 = __float2bfloat16(v0), h1 = __float2bfloat16(v1);
                    __nv_bfloat16 l0 = __float2bfloat16(v0 - __bfloat162float(h0));
                    __nv_bfloat16 l1 = __float2bfloat16(v1 - __bfloat162float(h1));
                    *reinterpret_cast<uint32_t*>(oH + (size_t)row * DD + cb) = pk(h0, h1);
                    *reinterpret_cast<uint32_t*>(oL + (size_t)row * DD + cb) = pk(l0, l1);
                } else if (MODE == 3) {
                    const int* mrow = maskp + bz * SS;
                    float s0 = v0 * 0.03125f, s1 = v1 * 0.03125f;
                    if (mrow[cb] == 0)     s0 = NEGV;
                    if (mrow[cb + 1] == 0) s1 = NEGV;
                    if (cb > row)     s0 += NEGV;
                    if (cb + 1 > row) s1 += NEGV;
                    float2 st = make_float2(s0, s1);
                    *reinterpret_cast<float2*>(g_p + (size_t)bz * SS * SS +
                                               (size_t)row * SS + cb) = st;
                } else {
                    float2 st = make_float2(v0, v1);
                    *reinterpret_cast<float2*>(outF + ((size_t)bz * SS + row) * NOUT + cb) = st;
                }
            }
        }
    }
}

// ---------------------------------------------------------------------------
// Row softmax, causal-restricted (fp32 in, split-bf16 out).
// Non-degenerate rows (some causal key allowed): future probs are exact fp32 0
//   -> max/exp/sum over cols<=row only; zero-fill the rest.
// Degenerate rows (all causal keys masked, rmax = -1e10): future scores are
//   synthesized from the mask (bit-identical to the materialized values).
// ---------------------------------------------------------------------------
__global__ __launch_bounds__(256) void softmax_kernel(const int* __restrict__ maskp) {
    const int row = blockIdx.x;
    const int bz = row >> 11, rloc = row & (SS - 1);
    const float* p = g_p + (size_t)row * SS;
    __nv_bfloat16* ph = g_ph + (size_t)row * SS;
    __nv_bfloat16* pl = g_pl + (size_t)row * SS;
    const int tid = threadIdx.x;
    const int csegs = rloc >> 8;             // segments containing causal cols

    float v[8];
    float mx = -INFINITY;
    #pragma unroll
    for (int s = 0; s < 8; s++) {
        const int idx = s * 256 + tid;
        v[s] = 0.f;
        if (s <= csegs && idx <= rloc) { v[s] = p[idx]; mx = fmaxf(mx, v[s]); }
    }
    #pragma unroll
    for (int o = 16; o > 0; o >>= 1) mx = fmaxf(mx, __shfl_xor_sync(0xffffffffu, mx, o));

    __shared__ float red[8];
    if ((tid & 31) == 0) red[tid >> 5] = mx;
    __syncthreads();
    float rmax = red[0];
    #pragma unroll
    for (int i = 1; i < 8; i++) rmax = fmaxf(rmax, red[i]);

    const bool deg = (rmax <= -5e9f);
    if (tid == 0) g_deg[row] = deg ? 1 : 0;

    float ssum = 0.f;
    if (!deg) {
        #pragma unroll
        for (int s = 0; s < 8; s++) {
            const int idx = s * 256 + tid;
            float e = 0.f;
            if (s <= csegs && idx <= rloc) e = expf(v[s] - rmax);
            v[s] = e; ssum += e;
        }
    } else {
        const int* mrow = maskp + bz * SS;
        #pragma unroll
        for (int s = 0; s < 8; s++) {
            const int idx = s * 256 + tid;
            float val;
            if (idx <= rloc) val = v[s];                                  // causal (all NEG here)
            else             val = (mrow[idx] == 0) ? (NEGV + NEGV) : NEGV; // synthesized future
            float e = expf(val - rmax);
            v[s] = e; ssum += e;
        }
    }
    #pragma unroll
    for (int o = 16; o > 0; o >>= 1) ssum += __shfl_xor_sync(0xffffffffu, ssum, o);
    __syncthreads();
    if ((tid & 31) == 0) red[tid >> 5] = ssum;
    __syncthreads();
    float tot = 0.f;
    #pragma unroll
    for (int i = 0; i < 8; i++) tot += red[i];

    const float inv = 1.0f / tot;
    #pragma unroll
    for (int s = 0; s < 8; s++) {
        float w = v[s] * inv;
        __nv_bfloat16 h = __float2bfloat16(w);
        __nv_bfloat16 l = __float2bfloat16(w - __bfloat162float(h));
        ph[s * 256 + tid] = h;
        pl[s * 256 + tid] = l;
    }
}

// ---------------------------------------------------------------------------
extern "C" void kernel_launch(void* const* d_in, const int* in_sizes, int n_in,
                              void* d_out, int out_size)
{
    (void)in_sizes; (void)n_in; (void)out_size;
    const float* Q    = (const float*)d_in[0];
    const float* Kin  = (const float*)d_in[1];
    const float* Vin  = (const float*)d_in[2];
    const int*   mask = (const int*)  d_in[3];
    const float* Wq   = (const float*)d_in[4];
    const float* bq   = (const float*)d_in[5];
    const float* Wk   = (const float*)d_in[6];
    const float* bk   = (const float*)d_in[7];
    const float* Wv   = (const float*)d_in[8];
    const float* bv   = (const float*)d_in[9];
    float* out = (float*)d_out;

    cudaFuncSetAttribute(gemm5<0>, cudaFuncAttributeMaxDynamicSharedMemorySize, SMEM_DYN);
    cudaFuncSetAttribute(gemm5<1>, cudaFuncAttributeMaxDynamicSharedMemorySize, SMEM_DYN);
    cudaFuncSetAttribute(gemm5<2>, cudaFuncAttributeMaxDynamicSharedMemorySize, SMEM_DYN);
    cudaFuncSetAttribute(gemm5<3>, cudaFuncAttributeMaxDynamicSharedMemorySize, SMEM_DYN);
    cudaFuncSetAttribute(gemm5<4>, cudaFuncAttributeMaxDynamicSharedMemorySize, SMEM_DYN);

    // 1) split all inputs/weights to hi/lo bf16
    cvt_all<<<dim3(2048, 6), 256>>>(Q, Kin, Vin, Wq, Wk, Wv);
    // 2,3) q/k projections: M = 8192 (batch-flat), N = 1024
    gemm5<0><<<dim3(8, 64, 1), 512, SMEM_DYN>>>(bq, nullptr, nullptr);
    gemm5<1><<<dim3(8, 64, 1), 512, SMEM_DYN>>>(bk, nullptr, nullptr);
    // 4) scores (4th launch -> profiled): per-batch 2048x2048, K = 1024
    gemm5<3><<<dim3(16, 16, NB), 512, SMEM_DYN>>>(nullptr, mask, nullptr);
    // 5) v projection
    gemm5<2><<<dim3(8, 64, 1), 512, SMEM_DYN>>>(bv, nullptr, nullptr);
    // 6) v transpose
    transpose_v<<<dim3(16, 32, NB), 256>>>();
    // 7) softmax (causal-restricted, sets degeneracy flags)
    softmax_kernel<<<NB * SS, 256>>>(mask);
    // 8) O = P @ V : per-batch 2048 x 1024, K causal-limited
    gemm5<4><<<dim3(8, 16, NB), 512, SMEM_DYN>>>(nullptr, nullptr, out);
}

// round 8
// speedup vs baseline: 2.1247x; 1.3052x over previous
#include <cuda_runtime.h>
#include <cuda_fp16.h>
#include <cstdint>
#include <math.h>

#define NB 4
#define SS 2048
#define DD 1024
#define NEGV (-1e10f)

// ---------------------------------------------------------------------------
// Device-global scratch (allocation-free per harness rules)
// fp16 split: X = X_h + X_l with fp16 hi/lo (11 bits each).
// 2-term GEMM: C = A_h*(B_h + B_l); A-side residual dropped (~2^-12 rel).
// => A-side tensors need HI only; B-side tensors need HI+LO.
// ---------------------------------------------------------------------------
__device__ __align__(128) __half g_Qh[NB*SS*DD];                 // A of q-proj
__device__ __align__(128) __half g_Kh[NB*SS*DD];                 // A of k-proj
__device__ __align__(128) __half g_Vh[NB*SS*DD];                 // A of v-proj
__device__ __align__(128) __half g_Wqh[DD*DD], g_Wql[DD*DD];     // B of projections
__device__ __align__(128) __half g_Wkh[DD*DD], g_Wkl[DD*DD];
__device__ __align__(128) __half g_Wvh[DD*DD], g_Wvl[DD*DD];
__device__ __align__(128) __half g_qh[NB*SS*DD];                 // A of scores (hi only)
__device__ __align__(128) __half g_kh[NB*SS*DD], g_kl[NB*SS*DD]; // B of scores
__device__ __align__(128) __half g_vh[NB*SS*DD], g_vl[NB*SS*DD]; // v (pre-transpose)
__device__ __align__(128) __half g_vth[NB*DD*SS], g_vtl[NB*DD*SS]; // B of PV [b][d][s]
__device__ float  g_p[(size_t)NB*SS*SS];                         // fp32 scores
__device__ __align__(128) __half g_ph[(size_t)NB*SS*SS];         // A of PV (hi only)
__device__ int    g_deg[NB*SS];                                  // degenerate-row flags

// ---------------------------------------------------------------------------
// helpers
// ---------------------------------------------------------------------------
__device__ __forceinline__ uint32_t s2u(const void* p) {
    return (uint32_t)__cvta_generic_to_shared(p);
}
__device__ __forceinline__ void cp16(uint32_t dst, const void* src) {
    asm volatile("cp.async.cg.shared.global [%0], [%1], 16;\n"
                 :: "r"(dst), "l"(src) : "memory");
}
__device__ __forceinline__ void cp_commit() {
    asm volatile("cp.async.commit_group;\n" ::: "memory");
}
__device__ __forceinline__ void cp_wait2() {
    asm volatile("cp.async.wait_group 2;\n" ::: "memory");
}
__device__ __forceinline__ uint32_t ld32s(uint32_t a) {
    uint32_t v;
    asm volatile("ld.shared.b32 %0, [%1];" : "=r"(v) : "r"(a));
    return v;
}
__device__ __forceinline__ void mma16816(float* c, const uint32_t* a, const uint32_t* b) {
    asm volatile("mma.sync.aligned.m16n8k16.row.col.f32.f16.f16.f32 "
        "{%0,%1,%2,%3}, {%4,%5,%6,%7}, {%8,%9}, {%0,%1,%2,%3};"
        : "+f"(c[0]), "+f"(c[1]), "+f"(c[2]), "+f"(c[3])
        : "r"(a[0]), "r"(a[1]), "r"(a[2]), "r"(a[3]), "r"(b[0]), "r"(b[1]));
}
__device__ __forceinline__ uint32_t pkh(__half a, __half b) {
    __half2 t = __halves2half2(a, b);
    return *reinterpret_cast<uint32_t*>(&t);
}

// ---------------------------------------------------------------------------
// One-shot fp32 -> fp16 conversion. QKV: hi only. Weights: hi + lo. MLP=4.
// ---------------------------------------------------------------------------
__global__ __launch_bounds__(256) void cvt_all(
    const float* __restrict__ Q, const float* __restrict__ K,
    const float* __restrict__ V, const float* __restrict__ Wq,
    const float* __restrict__ Wk, const float* __restrict__ Wv)
{
    const int seg = blockIdx.y;
    const float* src; __half *h, *l; int n4; bool wantlo;
    if      (seg == 0) { src = Q;  h = g_Qh;  l = nullptr; n4 = NB*SS*DD/4; wantlo = false; }
    else if (seg == 1) { src = K;  h = g_Kh;  l = nullptr; n4 = NB*SS*DD/4; wantlo = false; }
    else if (seg == 2) { src = V;  h = g_Vh;  l = nullptr; n4 = NB*SS*DD/4; wantlo = false; }
    else if (seg == 3) { src = Wq; h = g_Wqh; l = g_Wql;   n4 = DD*DD/4;   wantlo = true; }
    else if (seg == 4) { src = Wk; h = g_Wkh; l = g_Wkl;   n4 = DD*DD/4;   wantlo = true; }
    else               { src = Wv; h = g_Wvh; l = g_Wvl;   n4 = DD*DD/4;   wantlo = true; }

    const int base = (blockIdx.x * 256 + threadIdx.x) * 4;
    if (base >= n4) return;
    float4 v[4];
    #pragma unroll
    for (int i = 0; i < 4; i++) v[i] = reinterpret_cast<const float4*>(src)[base + i];
    #pragma unroll
    for (int i = 0; i < 4; i++) {
        __half h0 = __float2half_rn(v[i].x), h1 = __float2half_rn(v[i].y);
        __half h2 = __float2half_rn(v[i].z), h3 = __float2half_rn(v[i].w);
        reinterpret_cast<uint2*>(h)[base + i] = make_uint2(pkh(h0, h1), pkh(h2, h3));
        if (wantlo) {
            __half l0 = __float2half_rn(v[i].x - __half2float(h0));
            __half l1 = __float2half_rn(v[i].y - __half2float(h1));
            __half l2 = __float2half_rn(v[i].z - __half2float(h2));
            __half l3 = __float2half_rn(v[i].w - __half2float(h3));
            reinterpret_cast<uint2*>(l)[base + i] = make_uint2(pkh(l0, l1), pkh(l2, l3));
        }
    }
}

// ---------------------------------------------------------------------------
// v [b][s][d] -> vt [b][d][s] (hi and lo)
// ---------------------------------------------------------------------------
__global__ __launch_bounds__(256) void transpose_v() {
    __shared__ __half t[64][65];
    const int b = blockIdx.z, d0 = blockIdx.x * 64, s0 = blockIdx.y * 64;
    const int tid = threadIdx.x;
    const __half* srcs[2] = { g_vh, g_vl };
    __half*       dsts[2] = { g_vth, g_vtl };
    for (int p = 0; p < 2; p++) {
        const __half* src = srcs[p];
        __half* dst = dsts[p];
        for (int i = tid; i < 64 * 64; i += 256) {
            int r = i >> 6, c = i & 63;
            t[r][c] = src[((size_t)b * SS + s0 + r) * DD + d0 + c];
        }
        __syncthreads();
        for (int i = tid; i < 64 * 64; i += 256) {
            int r = i >> 6, c = i & 63;
            dst[((size_t)b * DD + d0 + r) * SS + s0 + c] = t[c][r];
        }
        __syncthreads();
    }
}

// ---------------------------------------------------------------------------
// 2-term fp16 GEMM on mma.sync: C[M,N] = A_h[M,K] * (B_h + B_l)[N,K]^T
//  MODE 0: q proj (writes q_h only)      MODE 1: k proj (writes k_h,k_l)
//  MODE 2: v proj (writes v_h,v_l)       MODE 3: scores (upper tiles skipped)
//  MODE 4: PV (causal K-limit; fp32 out)
// CTA 128x128, 512 threads (4x4 warps, 32x32 warp tile), K-chunk 32,
// 3-stage cp.async pipeline, row stride 80B. 16 MMAs + 24 LDS per kk.
// ---------------------------------------------------------------------------
#define RSTRIDE 80
#define BUFB (128 * RSTRIDE)           // 10240 per buffer
#define STAGEB (3 * BUFB)              // Ah|Bh|Bl = 30720
#define SMEM_DYN (3 * STAGEB)          // 92160

template <int MODE>
__device__ __forceinline__ void stage_cp(
    uint32_t stg, const __half* Ah, const __half* Bh, const __half* Bl,
    int m0, int n0, int k0, int tid)
{
    constexpr int LD = (MODE == 4) ? SS : DD;
    const int row = tid >> 2, seg = tid & 3;            // 512 threads: 128 rows x 4 segs
    const uint32_t d = (uint32_t)(row * RSTRIDE + seg * 16);
    const size_t ga = (size_t)(m0 + row) * LD + k0 + seg * 8;
    const size_t gb = (size_t)(n0 + row) * LD + k0 + seg * 8;
    cp16(stg + d,            Ah + ga);
    cp16(stg + BUFB + d,     Bh + gb);
    cp16(stg + 2 * BUFB + d, Bl + gb);
}

template <int MODE>
__global__ void __launch_bounds__(512, 1) gemm5(
    const float* __restrict__ bias, const int* __restrict__ maskp,
    float* __restrict__ outF)
{
    constexpr int KDIM = (MODE == 4) ? SS : DD;
    constexpr int NOUT = (MODE == 3) ? SS : DD;

    const int tid = threadIdx.x;
    const int wid = tid >> 5, lane = tid & 31;
    const int g = lane >> 2, t4 = lane & 3;
    const int wm = wid & 3, wn = wid >> 2;          // 4 x 4 warp grid, 32x32 warp tile
    const int bz = blockIdx.z;
    const int m0 = blockIdx.y * 128, n0 = blockIdx.x * 128;

    // ---- scores: strictly-future tiles are never read downstream ----
    if (MODE == 3 && blockIdx.x > blockIdx.y) return;

    // ---- PV: causal K-limit unless a degenerate row is present ----
    int nch = KDIM / 32;
    if (MODE == 4) {
        __shared__ int s_any;
        if (tid == 0) s_any = 0;
        __syncthreads();
        if (tid < 128 && g_deg[bz * SS + m0 + tid]) s_any = 1;
        __syncthreads();
        if (!s_any) nch = (m0 >> 5) + 4;     // K up to m0+128 only
    }

    const __half *Ah, *Bh, *Bl;
    __half *oH = nullptr, *oL = nullptr;
    if      (MODE == 0) { Ah = g_Qh; Bh = g_Wqh; Bl = g_Wql; oH = g_qh; }
    else if (MODE == 1) { Ah = g_Kh; Bh = g_Wkh; Bl = g_Wkl; oH = g_kh; oL = g_kl; }
    else if (MODE == 2) { Ah = g_Vh; Bh = g_Wvh; Bl = g_Wvl; oH = g_vh; oL = g_vl; }
    else if (MODE == 3) {
        Ah = g_qh + (size_t)bz * SS * DD;
        Bh = g_kh + (size_t)bz * SS * DD; Bl = g_kl + (size_t)bz * SS * DD;
    } else {
        Ah = g_ph + (size_t)bz * SS * SS;
        Bh = g_vth + (size_t)bz * DD * SS; Bl = g_vtl + (size_t)bz * DD * SS;
    }

    extern __shared__ char dsm[];
    const uint32_t sb = s2u(dsm);

    float c[2][4][4];
    #pragma unroll
    for (int mt = 0; mt < 2; mt++)
        #pragma unroll
        for (int nt = 0; nt < 4; nt++)
            #pragma unroll
            for (int i = 0; i < 4; i++) c[mt][nt][i] = 0.f;

    // prologue: stages 0, 1  (nch >= 4 always)
    stage_cp<MODE>(sb,          Ah, Bh, Bl, m0, n0, 0,  tid); cp_commit();
    stage_cp<MODE>(sb + STAGEB, Ah, Bh, Bl, m0, n0, 32, tid); cp_commit();

    for (int ch = 0; ch < nch; ch++) {
        if (ch + 2 < nch)
            stage_cp<MODE>(sb + ((ch + 2) % 3) * STAGEB, Ah, Bh, Bl,
                           m0, n0, (ch + 2) * 32, tid);
        cp_commit();
        cp_wait2();
        __syncthreads();

        const uint32_t stg = sb + (ch % 3) * STAGEB;
        const uint32_t sAh = stg;
        const uint32_t sBh = stg + BUFB, sBl = stg + 2 * BUFB;

        #pragma unroll
        for (int kk = 0; kk < 2; kk++) {
            const uint32_t kb = (uint32_t)(kk * 32 + t4 * 4);
            uint32_t ah[2][4], bh[4][2], bl[4][2];
            #pragma unroll
            for (int mt = 0; mt < 2; mt++) {
                const uint32_t r0 = (uint32_t)((wm * 32 + mt * 16 + g) * RSTRIDE) + kb;
                ah[mt][0] = ld32s(sAh + r0);
                ah[mt][1] = ld32s(sAh + r0 + 8 * RSTRIDE);
                ah[mt][2] = ld32s(sAh + r0 + 16);
                ah[mt][3] = ld32s(sAh + r0 + 8 * RSTRIDE + 16);
            }
            #pragma unroll
            for (int nt = 0; nt < 4; nt++) {
                const uint32_t r0 = (uint32_t)((wn * 32 + nt * 8 + g) * RSTRIDE) + kb;
                bh[nt][0] = ld32s(sBh + r0);
                bh[nt][1] = ld32s(sBh + r0 + 16);
                bl[nt][0] = ld32s(sBl + r0);
                bl[nt][1] = ld32s(sBl + r0 + 16);
            }
            #pragma unroll
            for (int mt = 0; mt < 2; mt++)
                #pragma unroll
                for (int nt = 0; nt < 4; nt++) {
                    mma16816(c[mt][nt], ah[mt], bh[nt]);   // A_h * B_h
                    mma16816(c[mt][nt], ah[mt], bl[nt]);   // A_h * B_l
                }
        }
        __syncthreads();
    }

    // ---- epilogue ----
    #pragma unroll
    for (int mt = 0; mt < 2; mt++) {
        #pragma unroll
        for (int half = 0; half < 2; half++) {
            const int row = m0 + wm * 32 + mt * 16 + g + half * 8;
            #pragma unroll
            for (int nt = 0; nt < 4; nt++) {
                const int cb = n0 + wn * 32 + nt * 8 + t4 * 2;
                float v0 = c[mt][nt][half * 2];
                float v1 = c[mt][nt][half * 2 + 1];
                if (MODE == 0) {
                    v0 += bias[cb]; v1 += bias[cb + 1];
                    *reinterpret_cast<uint32_t*>(oH + (size_t)row * DD + cb) =
                        pkh(__float2half_rn(v0), __float2half_rn(v1));
                } else if (MODE <= 2) {
                    v0 += bias[cb]; v1 += bias[cb + 1];
                    __half h0 = __float2half_rn(v0), h1 = __float2half_rn(v1);
                    __half l0 = __float2half_rn(v0 - __half2float(h0));
                    __half l1 = __float2half_rn(v1 - __half2float(h1));
                    *reinterpret_cast<uint32_t*>(oH + (size_t)row * DD + cb) = pkh(h0, h1);
                    *reinterpret_cast<uint32_t*>(oL + (size_t)row * DD + cb) = pkh(l0, l1);
                } else if (MODE == 3) {
                    const int* mrow = maskp + bz * SS;
                    float s0 = v0 * 0.03125f, s1 = v1 * 0.03125f;
                    if (mrow[cb] == 0)     s0 = NEGV;
                    if (mrow[cb + 1] == 0) s1 = NEGV;
                    if (cb > row)     s0 += NEGV;
                    if (cb + 1 > row) s1 += NEGV;
                    float2 st = make_float2(s0, s1);
                    *reinterpret_cast<float2*>(g_p + (size_t)bz * SS * SS +
                                               (size_t)row * SS + cb) = st;
                } else {
                    float2 st = make_float2(v0, v1);
                    *reinterpret_cast<float2*>(outF + ((size_t)bz * SS + row) * NOUT + cb) = st;
                }
            }
        }
    }
}

// ---------------------------------------------------------------------------
// Row softmax, causal-restricted (fp32 in, fp16 out).
// Degenerate rows synthesize future scores from the mask (bit-identical).
// ---------------------------------------------------------------------------
__global__ __launch_bounds__(256) void softmax_kernel(const int* __restrict__ maskp) {
    const int row = blockIdx.x;
    const int bz = row >> 11, rloc = row & (SS - 1);
    const float* p = g_p + (size_t)row * SS;
    __half* ph = g_ph + (size_t)row * SS;
    const int tid = threadIdx.x;
    const int csegs = rloc >> 8;             // segments containing causal cols

    float v[8];
    float mx = -INFINITY;
    #pragma unroll
    for (int s = 0; s < 8; s++) {
        const int idx = s * 256 + tid;
        v[s] = 0.f;
        if (s <= csegs && idx <= rloc) { v[s] = p[idx]; mx = fmaxf(mx, v[s]); }
    }
    #pragma unroll
    for (int o = 16; o > 0; o >>= 1) mx = fmaxf(mx, __shfl_xor_sync(0xffffffffu, mx, o));

    __shared__ float red[8];
    if ((tid & 31) == 0) red[tid >> 5] = mx;
    __syncthreads();
    float rmax = red[0];
    #pragma unroll
    for (int i = 1; i < 8; i++) rmax = fmaxf(rmax, red[i]);

    const bool deg = (rmax <= -5e9f);
    if (tid == 0) g_deg[row] = deg ? 1 : 0;

    float ssum = 0.f;
    if (!deg) {
        #pragma unroll
        for (int s = 0; s < 8; s++) {
            const int idx = s * 256 + tid;
            float e = 0.f;
            if (s <= csegs && idx <= rloc) e = expf(v[s] - rmax);
            v[s] = e; ssum += e;
        }
    } else {
        const int* mrow = maskp + bz * SS;
        #pragma unroll
        for (int s = 0; s < 8; s++) {
            const int idx = s * 256 + tid;
            float val;
            if (idx <= rloc) val = v[s];                                    // causal (all NEG)
            else             val = (mrow[idx] == 0) ? (NEGV + NEGV) : NEGV; // synthesized future
            float e = expf(val - rmax);
            v[s] = e; ssum += e;
        }
    }
    #pragma unroll
    for (int o = 16; o > 0; o >>= 1) ssum += __shfl_xor_sync(0xffffffffu, ssum, o);
    __syncthreads();
    if ((tid & 31) == 0) red[tid >> 5] = ssum;
    __syncthreads();
    float tot = 0.f;
    #pragma unroll
    for (int i = 0; i < 8; i++) tot += red[i];

    const float inv = 1.0f / tot;
    #pragma unroll
    for (int s = 0; s < 8; s++)
        ph[s * 256 + tid] = __float2half_rn(v[s] * inv);
}

// ---------------------------------------------------------------------------
extern "C" void kernel_launch(void* const* d_in, const int* in_sizes, int n_in,
                              void* d_out, int out_size)
{
    (void)in_sizes; (void)n_in; (void)out_size;
    const float* Q    = (const float*)d_in[0];
    const float* Kin  = (const float*)d_in[1];
    const float* Vin  = (const float*)d_in[2];
    const int*   mask = (const int*)  d_in[3];
    const float* Wq   = (const float*)d_in[4];
    const float* bq   = (const float*)d_in[5];
    const float* Wk   = (const float*)d_in[6];
    const float* bk   = (const float*)d_in[7];
    const float* Wv   = (const float*)d_in[8];
    const float* bv   = (const float*)d_in[9];
    float* out = (float*)d_out;

    cudaFuncSetAttribute(gemm5<0>, cudaFuncAttributeMaxDynamicSharedMemorySize, SMEM_DYN);
    cudaFuncSetAttribute(gemm5<1>, cudaFuncAttributeMaxDynamicSharedMemorySize, SMEM_DYN);
    cudaFuncSetAttribute(gemm5<2>, cudaFuncAttributeMaxDynamicSharedMemorySize, SMEM_DYN);
    cudaFuncSetAttribute(gemm5<3>, cudaFuncAttributeMaxDynamicSharedMemorySize, SMEM_DYN);
    cudaFuncSetAttribute(gemm5<4>, cudaFuncAttributeMaxDynamicSharedMemorySize, SMEM_DYN);

    // 1) fp16 conversion (QKV hi-only, weights hi+lo)
    cvt_all<<<dim3(2048, 6), 256>>>(Q, Kin, Vin, Wq, Wk, Wv);
    // 2,3) q/k projections: M = 8192 (batch-flat), N = 1024
    gemm5<0><<<dim3(8, 64, 1), 512, SMEM_DYN>>>(bq, nullptr, nullptr);
    gemm5<1><<<dim3(8, 64, 1), 512, SMEM_DYN>>>(bk, nullptr, nullptr);
    // 4) scores (4th launch -> profiled): per-batch 2048x2048, K = 1024
    gemm5<3><<<dim3(16, 16, NB), 512, SMEM_DYN>>>(nullptr, mask, nullptr);
    // 5) v projection
    gemm5<2><<<dim3(8, 64, 1), 512, SMEM_DYN>>>(bv, nullptr, nullptr);
    // 6) v transpose
    transpose_v<<<dim3(16, 32, NB), 256>>>();
    // 7) softmax (causal-restricted, sets degeneracy flags)
    softmax_kernel<<<NB * SS, 256>>>(mask);
    // 8) O = P @ V : per-batch 2048 x 1024, K causal-limited
    gemm5<4><<<dim3(8, 16, NB), 512, SMEM_DYN>>>(nullptr, nullptr, out);
}

// round 9
// speedup vs baseline: 2.4652x; 1.1602x over previous
#include <cuda_runtime.h>
#include <cuda_fp16.h>
#include <cstdint>
#include <math.h>

#define NB 4
#define SS 2048
#define DD 1024
#define NEGV (-1e10f)

// ---------------------------------------------------------------------------
// Device-global scratch. fp16 2-term split: C = A_h * (B_h + B_l).
// A-side tensors hi only; B-side tensors hi+lo.
// ---------------------------------------------------------------------------
__device__ __align__(128) __half g_Qh[NB*SS*DD];
__device__ __align__(128) __half g_Kh[NB*SS*DD];
__device__ __align__(128) __half g_Vh[NB*SS*DD];
__device__ __align__(128) __half g_Wqh[DD*DD], g_Wql[DD*DD];
__device__ __align__(128) __half g_Wkh[DD*DD], g_Wkl[DD*DD];
__device__ __align__(128) __half g_Wvh[DD*DD], g_Wvl[DD*DD];
__device__ __align__(128) __half g_qh[NB*SS*DD];
__device__ __align__(128) __half g_kh[NB*SS*DD], g_kl[NB*SS*DD];
__device__ __align__(128) __half g_vh[NB*SS*DD], g_vl[NB*SS*DD];
__device__ __align__(128) __half g_vth[NB*DD*SS], g_vtl[NB*DD*SS];  // [b][d][s]
__device__ float  g_p[(size_t)NB*SS*SS];
__device__ __align__(128) __half g_ph[(size_t)NB*SS*SS];
__device__ int    g_deg[NB*SS];

// ---------------------------------------------------------------------------
// helpers
// ---------------------------------------------------------------------------
__device__ __forceinline__ uint32_t s2u(const void* p) {
    return (uint32_t)__cvta_generic_to_shared(p);
}
__device__ __forceinline__ void cp16(uint32_t dst, const void* src) {
    asm volatile("cp.async.cg.shared.global [%0], [%1], 16;\n"
                 :: "r"(dst), "l"(src) : "memory");
}
__device__ __forceinline__ void cp_commit() {
    asm volatile("cp.async.commit_group;\n" ::: "memory");
}
__device__ __forceinline__ void cp_wait2() {
    asm volatile("cp.async.wait_group 2;\n" ::: "memory");
}
__device__ __forceinline__ void ldsm4(uint32_t& r0, uint32_t& r1, uint32_t& r2,
                                      uint32_t& r3, uint32_t a) {
    asm volatile("ldmatrix.sync.aligned.m8n8.x4.shared.b16 {%0,%1,%2,%3}, [%4];"
        : "=r"(r0), "=r"(r1), "=r"(r2), "=r"(r3) : "r"(a));
}
__device__ __forceinline__ void mma16816(float* c, const uint32_t* a, const uint32_t* b) {
    asm volatile("mma.sync.aligned.m16n8k16.row.col.f32.f16.f16.f32 "
        "{%0,%1,%2,%3}, {%4,%5,%6,%7}, {%8,%9}, {%0,%1,%2,%3};"
        : "+f"(c[0]), "+f"(c[1]), "+f"(c[2]), "+f"(c[3])
        : "r"(a[0]), "r"(a[1]), "r"(a[2]), "r"(a[3]), "r"(b[0]), "r"(b[1]));
}
__device__ __forceinline__ uint32_t pkh(__half a, __half b) {
    __half2 t = __halves2half2(a, b);
    return *reinterpret_cast<uint32_t*>(&t);
}

// ---------------------------------------------------------------------------
// One-shot fp32 -> fp16 conversion. QKV: hi only. Weights: hi + lo. MLP=4.
// ---------------------------------------------------------------------------
__global__ __launch_bounds__(256) void cvt_all(
    const float* __restrict__ Q, const float* __restrict__ K,
    const float* __restrict__ V, const float* __restrict__ Wq,
    const float* __restrict__ Wk, const float* __restrict__ Wv)
{
    const int seg = blockIdx.y;
    const float* src; __half *h, *l; int n4; bool wantlo;
    if      (seg == 0) { src = Q;  h = g_Qh;  l = nullptr; n4 = NB*SS*DD/4; wantlo = false; }
    else if (seg == 1) { src = K;  h = g_Kh;  l = nullptr; n4 = NB*SS*DD/4; wantlo = false; }
    else if (seg == 2) { src = V;  h = g_Vh;  l = nullptr; n4 = NB*SS*DD/4; wantlo = false; }
    else if (seg == 3) { src = Wq; h = g_Wqh; l = g_Wql;   n4 = DD*DD/4;   wantlo = true; }
    else if (seg == 4) { src = Wk; h = g_Wkh; l = g_Wkl;   n4 = DD*DD/4;   wantlo = true; }
    else               { src = Wv; h = g_Wvh; l = g_Wvl;   n4 = DD*DD/4;   wantlo = true; }

    const int base = (blockIdx.x * 256 + threadIdx.x) * 4;
    if (base >= n4) return;
    float4 v[4];
    #pragma unroll
    for (int i = 0; i < 4; i++) v[i] = reinterpret_cast<const float4*>(src)[base + i];
    #pragma unroll
    for (int i = 0; i < 4; i++) {
        __half h0 = __float2half_rn(v[i].x), h1 = __float2half_rn(v[i].y);
        __half h2 = __float2half_rn(v[i].z), h3 = __float2half_rn(v[i].w);
        reinterpret_cast<uint2*>(h)[base + i] = make_uint2(pkh(h0, h1), pkh(h2, h3));
        if (wantlo) {
            __half l0 = __float2half_rn(v[i].x - __half2float(h0));
            __half l1 = __float2half_rn(v[i].y - __half2float(h1));
            __half l2 = __float2half_rn(v[i].z - __half2float(h2));
            __half l3 = __float2half_rn(v[i].w - __half2float(h3));
            reinterpret_cast<uint2*>(l)[base + i] = make_uint2(pkh(l0, l1), pkh(l2, l3));
        }
    }
}

// ---------------------------------------------------------------------------
// v [b][s][d] -> vt [b][d][s] (hi and lo)
// ---------------------------------------------------------------------------
__global__ __launch_bounds__(256) void transpose_v() {
    __shared__ __half t[64][65];
    const int b = blockIdx.z, d0 = blockIdx.x * 64, s0 = blockIdx.y * 64;
    const int tid = threadIdx.x;
    const __half* srcs[2] = { g_vh, g_vl };
    __half*       dsts[2] = { g_vth, g_vtl };
    for (int p = 0; p < 2; p++) {
        const __half* src = srcs[p];
        __half* dst = dsts[p];
        for (int i = tid; i < 64 * 64; i += 256) {
            int r = i >> 6, c = i & 63;
            t[r][c] = src[((size_t)b * SS + s0 + r) * DD + d0 + c];
        }
        __syncthreads();
        for (int i = tid; i < 64 * 64; i += 256) {
            int r = i >> 6, c = i & 63;
            dst[((size_t)b * DD + d0 + r) * SS + s0 + c] = t[c][r];
        }
        __syncthreads();
    }
}

// ---------------------------------------------------------------------------
// 2-term fp16 GEMM, NT: C[M,N] = A_h[M,K] * (B_h + B_l)[N,K]^T
//  MODE 5: merged projections (blockIdx.z: 0=q hi-only, 1=k hi+lo, 2=v hi+lo)
//  MODE 3: scores (strictly-upper tiles skipped; scale+mask epilogue)
//  MODE 4: PV (causal K-limit via flags; fp32 out)
// CTA 128x128, 512 threads (4x4 warps, 32x32 warp tile), K-chunk 64,
// 3-stage cp.async pipeline, row stride 144B, ldmatrix fragment loads.
// ---------------------------------------------------------------------------
#define RS 144
#define BUFB (128 * RS)                // 18432 per buffer
#define STAGEB (3 * BUFB)              // Ah|Bh|Bl = 55296
#define SMEM_DYN (3 * STAGEB)          // 165888

template <int MODE>
__device__ __forceinline__ void stage_cp(
    uint32_t stg, const __half* Ah, const __half* Bh, const __half* Bl,
    int m0, int n0, int k0, int tid)
{
    constexpr int LD = (MODE == 4) ? SS : DD;
    const int row = tid >> 2, seg = tid & 3;        // 128 rows x 4 segs, 2 cp16 each
    const uint32_t d = (uint32_t)(row * RS + seg * 16);
    const size_t ga = (size_t)(m0 + row) * LD + k0 + seg * 8;
    const size_t gb = (size_t)(n0 + row) * LD + k0 + seg * 8;
    cp16(stg + d,               Ah + ga);
    cp16(stg + d + 64,          Ah + ga + 32);
    cp16(stg + BUFB + d,        Bh + gb);
    cp16(stg + BUFB + d + 64,   Bh + gb + 32);
    cp16(stg + 2*BUFB + d,      Bl + gb);
    cp16(stg + 2*BUFB + d + 64, Bl + gb + 32);
}

template <int MODE>
__global__ void __launch_bounds__(512, 1) gemmX(
    const float* __restrict__ bq, const float* __restrict__ bk,
    const float* __restrict__ bvp, const int* __restrict__ maskp,
    float* __restrict__ outF)
{
    constexpr int KDIM = (MODE == 4) ? SS : DD;

    const int tid = threadIdx.x;
    const int wid = tid >> 5, lane = tid & 31;
    const int g = lane >> 2, t4 = lane & 3;
    const int wm = wid & 3, wn = wid >> 2;          // 4x4 warp grid, 32x32 warp tile
    const int bz = blockIdx.z;
    const int m0 = blockIdx.y * 128, n0 = blockIdx.x * 128;

    // scores: strictly-future tiles never read downstream
    if (MODE == 3 && blockIdx.x > blockIdx.y) return;

    // PV: causal K-limit unless a degenerate row present
    int nch = KDIM / 64;
    if (MODE == 4) {
        __shared__ int s_any;
        if (tid == 0) s_any = 0;
        __syncthreads();
        if (tid < 128 && g_deg[bz * SS + m0 + tid]) s_any = 1;
        __syncthreads();
        if (!s_any) nch = (m0 >> 6) + 2;            // K up to m0+128 only
    }

    const __half *Ah, *Bh, *Bl;
    const float* bias = nullptr;
    __half *oH = nullptr, *oL = nullptr;
    if (MODE == 5) {
        if (bz == 0)      { Ah = g_Qh; Bh = g_Wqh; Bl = g_Wql; bias = bq;  oH = g_qh; }
        else if (bz == 1) { Ah = g_Kh; Bh = g_Wkh; Bl = g_Wkl; bias = bk;  oH = g_kh; oL = g_kl; }
        else              { Ah = g_Vh; Bh = g_Wvh; Bl = g_Wvl; bias = bvp; oH = g_vh; oL = g_vl; }
    } else if (MODE == 3) {
        Ah = g_qh + (size_t)bz * SS * DD;
        Bh = g_kh + (size_t)bz * SS * DD; Bl = g_kl + (size_t)bz * SS * DD;
    } else {
        Ah = g_ph + (size_t)bz * SS * SS;
        Bh = g_vth + (size_t)bz * DD * SS; Bl = g_vtl + (size_t)bz * DD * SS;
    }

    extern __shared__ char dsm[];
    const uint32_t sb = s2u(dsm);

    // ldmatrix lane address components
    const int part = lane >> 3;
    const int aRow = (part & 1) * 8 + (lane & 7);   // A: m within 16, parts 0/1
    const int aK   = (part >> 1) * 16;              //    k halves 0-7 / 8-15
    const int bRow = (part >> 1) * 8 + (lane & 7);  // B: n within 16, parts 0/2
    const int bK   = (part & 1) * 16;               //    k halves 0-7 / 8-15

    float c[2][4][4];
    #pragma unroll
    for (int mt = 0; mt < 2; mt++)
        #pragma unroll
        for (int nt = 0; nt < 4; nt++)
            #pragma unroll
            for (int i = 0; i < 4; i++) c[mt][nt][i] = 0.f;

    // prologue: stages 0, 1 (nch >= 2 always)
    stage_cp<MODE>(sb,          Ah, Bh, Bl, m0, n0, 0,  tid); cp_commit();
    stage_cp<MODE>(sb + STAGEB, Ah, Bh, Bl, m0, n0, 64, tid); cp_commit();

    for (int ch = 0; ch < nch; ch++) {
        if (ch + 2 < nch)
            stage_cp<MODE>(sb + ((ch + 2) % 3) * STAGEB, Ah, Bh, Bl,
                           m0, n0, (ch + 2) * 64, tid);
        cp_commit();
        cp_wait2();
        __syncthreads();

        const uint32_t stg = sb + (ch % 3) * STAGEB;
        const uint32_t sAh = stg;
        const uint32_t sBh = stg + BUFB, sBl = stg + 2 * BUFB;

        #pragma unroll
        for (int kk = 0; kk < 4; kk++) {
            const uint32_t kb = (uint32_t)(kk * 32);
            uint32_t ah[2][4], bh[8], bl[8];
            #pragma unroll
            for (int mt = 0; mt < 2; mt++)
                ldsm4(ah[mt][0], ah[mt][1], ah[mt][2], ah[mt][3],
                      sAh + (uint32_t)((wm * 32 + mt * 16 + aRow) * RS) + aK + kb);
            #pragma unroll
            for (int p = 0; p < 2; p++) {
                const uint32_t br = (uint32_t)((wn * 32 + p * 16 + bRow) * RS) + bK + kb;
                ldsm4(bh[4*p], bh[4*p+1], bh[4*p+2], bh[4*p+3], sBh + br);
                ldsm4(bl[4*p], bl[4*p+1], bl[4*p+2], bl[4*p+3], sBl + br);
            }
            #pragma unroll
            for (int mt = 0; mt < 2; mt++)
                #pragma unroll
                for (int nt = 0; nt < 4; nt++) {
                    mma16816(c[mt][nt], ah[mt], bh + 2 * nt);   // A_h * B_h
                    mma16816(c[mt][nt], ah[mt], bl + 2 * nt);   // A_h * B_l
                }
        }
        __syncthreads();
    }

    // ---- epilogue ----
    #pragma unroll
    for (int mt = 0; mt < 2; mt++) {
        #pragma unroll
        for (int half = 0; half < 2; half++) {
            const int row = m0 + wm * 32 + mt * 16 + g + half * 8;
            #pragma unroll
            for (int nt = 0; nt < 4; nt++) {
                const int cb = n0 + wn * 32 + nt * 8 + t4 * 2;
                float v0 = c[mt][nt][half * 2];
                float v1 = c[mt][nt][half * 2 + 1];
                if (MODE == 5) {
                    v0 += bias[cb]; v1 += bias[cb + 1];
                    __half h0 = __float2half_rn(v0), h1 = __float2half_rn(v1);
                    *reinterpret_cast<uint32_t*>(oH + (size_t)row * DD + cb) = pkh(h0, h1);
                    if (oL) {
                        __half l0 = __float2half_rn(v0 - __half2float(h0));
                        __half l1 = __float2half_rn(v1 - __half2float(h1));
                        *reinterpret_cast<uint32_t*>(oL + (size_t)row * DD + cb) = pkh(l0, l1);
                    }
                } else if (MODE == 3) {
                    const int* mrow = maskp + bz * SS;
                    float s0 = v0 * 0.03125f, s1 = v1 * 0.03125f;
                    if (mrow[cb] == 0)     s0 = NEGV;
                    if (mrow[cb + 1] == 0) s1 = NEGV;
                    if (cb > row)     s0 += NEGV;
                    if (cb + 1 > row) s1 += NEGV;
                    float2 st = make_float2(s0, s1);
                    *reinterpret_cast<float2*>(g_p + (size_t)bz * SS * SS +
                                               (size_t)row * SS + cb) = st;
                } else {
                    float2 st = make_float2(v0, v1);
                    *reinterpret_cast<float2*>(outF + ((size_t)bz * SS + row) * DD + cb) = st;
                }
            }
        }
    }
}

// ---------------------------------------------------------------------------
// Row softmax, causal-restricted (fp32 in, fp16 out).
// Degenerate rows synthesize future scores from the mask (bit-identical).
// ---------------------------------------------------------------------------
__global__ __launch_bounds__(256) void softmax_kernel(const int* __restrict__ maskp) {
    const int row = blockIdx.x;
    const int bz = row >> 11, rloc = row & (SS - 1);
    const float* p = g_p + (size_t)row * SS;
    __half* ph = g_ph + (size_t)row * SS;
    const int tid = threadIdx.x;
    const int csegs = rloc >> 8;

    float v[8];
    float mx = -INFINITY;
    #pragma unroll
    for (int s = 0; s < 8; s++) {
        const int idx = s * 256 + tid;
        v[s] = 0.f;
        if (s <= csegs && idx <= rloc) { v[s] = p[idx]; mx = fmaxf(mx, v[s]); }
    }
    #pragma unroll
    for (int o = 16; o > 0; o >>= 1) mx = fmaxf(mx, __shfl_xor_sync(0xffffffffu, mx, o));

    __shared__ float red[8];
    if ((tid & 31) == 0) red[tid >> 5] = mx;
    __syncthreads();
    float rmax = red[0];
    #pragma unroll
    for (int i = 1; i < 8; i++) rmax = fmaxf(rmax, red[i]);

    const bool deg = (rmax <= -5e9f);
    if (tid == 0) g_deg[row] = deg ? 1 : 0;

    float ssum = 0.f;
    if (!deg) {
        #pragma unroll
        for (int s = 0; s < 8; s++) {
            const int idx = s * 256 + tid;
            float e = 0.f;
            if (s <= csegs && idx <= rloc) e = expf(v[s] - rmax);
            v[s] = e; ssum += e;
        }
    } else {
        const int* mrow = maskp + bz * SS;
        #pragma unroll
        for (int s = 0; s < 8; s++) {
            const int idx = s * 256 + tid;
            float val;
            if (idx <= rloc) val = v[s];
            else             val = (mrow[idx] == 0) ? (NEGV + NEGV) : NEGV;
            float e = expf(val - rmax);
            v[s] = e; ssum += e;
        }
    }
    #pragma unroll
    for (int o = 16; o > 0; o >>= 1) ssum += __shfl_xor_sync(0xffffffffu, ssum, o);
    __syncthreads();
    if ((tid & 31) == 0) red[tid >> 5] = ssum;
    __syncthreads();
    float tot = 0.f;
    #pragma unroll
    for (int i = 0; i < 8; i++) tot += red[i];

    const float inv = 1.0f / tot;
    #pragma unroll
    for (int s = 0; s < 8; s++)
        ph[s * 256 + tid] = __float2half_rn(v[s] * inv);
}

// ---------------------------------------------------------------------------
extern "C" void kernel_launch(void* const* d_in, const int* in_sizes, int n_in,
                              void* d_out, int out_size)
{
    (void)in_sizes; (void)n_in; (void)out_size;
    const float* Q    = (const float*)d_in[0];
    const float* Kin  = (const float*)d_in[1];
    const float* Vin  = (const float*)d_in[2];
    const int*   mask = (const int*)  d_in[3];
    const float* Wq   = (const float*)d_in[4];
    const float* bq   = (const float*)d_in[5];
    const float* Wk   = (const float*)d_in[6];
    const float* bk   = (const float*)d_in[7];
    const float* Wv   = (const float*)d_in[8];
    const float* bv   = (const float*)d_in[9];
    float* out = (float*)d_out;

    cudaFuncSetAttribute(gemmX<5>, cudaFuncAttributeMaxDynamicSharedMemorySize, SMEM_DYN);
    cudaFuncSetAttribute(gemmX<3>, cudaFuncAttributeMaxDynamicSharedMemorySize, SMEM_DYN);
    cudaFuncSetAttribute(gemmX<4>, cudaFuncAttributeMaxDynamicSharedMemorySize, SMEM_DYN);

    // 1) fp16 conversion (QKV hi-only, weights hi+lo)
    cvt_all<<<dim3(2048, 6), 256>>>(Q, Kin, Vin, Wq, Wk, Wv);
    // 2) merged q/k/v projections: M = 8192, N = 1024, z = tensor select
    gemmX<5><<<dim3(8, 64, 3), 512, SMEM_DYN>>>(bq, bk, bv, nullptr, nullptr);
    // 3) v transpose
    transpose_v<<<dim3(16, 32, NB), 256>>>();
    // 4) scores (4th launch -> profiled): per-batch 2048x2048, K = 1024
    gemmX<3><<<dim3(16, 16, NB), 512, SMEM_DYN>>>(nullptr, nullptr, nullptr, mask, nullptr);
    // 5) softmax (causal-restricted, sets degeneracy flags)
    softmax_kernel<<<NB * SS, 256>>>(mask);
    // 6) O = P @ V : per-batch 2048 x 1024, K causal-limited
    gemmX<4><<<dim3(8, 16, NB), 512, SMEM_DYN>>>(nullptr, nullptr, nullptr, nullptr, out);
}

// round 10
// speedup vs baseline: 2.7930x; 1.1330x over previous
#include <cuda_runtime.h>
#include <cuda_fp16.h>
#include <cstdint>
#include <math.h>

#define NB 4
#define SS 2048
#define DD 1024
#define NEGV (-1e10f)

// ---------------------------------------------------------------------------
// Device-global scratch. fp16 2-term split: C = A_h * (B_h + B_l).
// A-side tensors hi only; B-side tensors hi+lo.
// ---------------------------------------------------------------------------
__device__ __align__(128) __half g_Qh[NB*SS*DD];
__device__ __align__(128) __half g_Kh[NB*SS*DD];
__device__ __align__(128) __half g_Vh[NB*SS*DD];
__device__ __align__(128) __half g_Wqh[DD*DD], g_Wql[DD*DD];
__device__ __align__(128) __half g_Wkh[DD*DD], g_Wkl[DD*DD];
__device__ __align__(128) __half g_Wvh[DD*DD], g_Wvl[DD*DD];
__device__ __align__(128) __half g_qh[NB*SS*DD];
__device__ __align__(128) __half g_kh[NB*SS*DD], g_kl[NB*SS*DD];
__device__ __align__(128) __half g_vh[NB*SS*DD], g_vl[NB*SS*DD];
__device__ __align__(128) __half g_vth[NB*DD*SS], g_vtl[NB*DD*SS];  // [b][d][s]
__device__ float  g_p[(size_t)NB*SS*SS];
__device__ __align__(128) __half g_ph[(size_t)NB*SS*SS];
__device__ int    g_deg[NB*SS];

// ---------------------------------------------------------------------------
// helpers
// ---------------------------------------------------------------------------
__device__ __forceinline__ uint32_t s2u(const void* p) {
    return (uint32_t)__cvta_generic_to_shared(p);
}
__device__ __forceinline__ void cp16(uint32_t dst, const void* src) {
    asm volatile("cp.async.cg.shared.global [%0], [%1], 16;\n"
                 :: "r"(dst), "l"(src) : "memory");
}
__device__ __forceinline__ void cp_commit() {
    asm volatile("cp.async.commit_group;\n" ::: "memory");
}
__device__ __forceinline__ void cp_wait2() {
    asm volatile("cp.async.wait_group 2;\n" ::: "memory");
}
__device__ __forceinline__ void ldsm4(uint32_t& r0, uint32_t& r1, uint32_t& r2,
                                      uint32_t& r3, uint32_t a) {
    asm volatile("ldmatrix.sync.aligned.m8n8.x4.shared.b16 {%0,%1,%2,%3}, [%4];"
        : "=r"(r0), "=r"(r1), "=r"(r2), "=r"(r3) : "r"(a));
}
__device__ __forceinline__ void mma16816(float* c, const uint32_t* a, const uint32_t* b) {
    asm volatile("mma.sync.aligned.m16n8k16.row.col.f32.f16.f16.f32 "
        "{%0,%1,%2,%3}, {%4,%5,%6,%7}, {%8,%9}, {%0,%1,%2,%3};"
        : "+f"(c[0]), "+f"(c[1]), "+f"(c[2]), "+f"(c[3])
        : "r"(a[0]), "r"(a[1]), "r"(a[2]), "r"(a[3]), "r"(b[0]), "r"(b[1]));
}
__device__ __forceinline__ uint32_t pkh(__half a, __half b) {
    __half2 t = __halves2half2(a, b);
    return *reinterpret_cast<uint32_t*>(&t);
}

// ---------------------------------------------------------------------------
// One-shot fp32 -> fp16 conversion. QKV: hi only. Weights: hi + lo. MLP=4.
// ---------------------------------------------------------------------------
__global__ __launch_bounds__(256) void cvt_all(
    const float* __restrict__ Q, const float* __restrict__ K,
    const float* __restrict__ V, const float* __restrict__ Wq,
    const float* __restrict__ Wk, const float* __restrict__ Wv)
{
    const int seg = blockIdx.y;
    const float* src; __half *h, *l; int n4; bool wantlo;
    if      (seg == 0) { src = Q;  h = g_Qh;  l = nullptr; n4 = NB*SS*DD/4; wantlo = false; }
    else if (seg == 1) { src = K;  h = g_Kh;  l = nullptr; n4 = NB*SS*DD/4; wantlo = false; }
    else if (seg == 2) { src = V;  h = g_Vh;  l = nullptr; n4 = NB*SS*DD/4; wantlo = false; }
    else if (seg == 3) { src = Wq; h = g_Wqh; l = g_Wql;   n4 = DD*DD/4;   wantlo = true; }
    else if (seg == 4) { src = Wk; h = g_Wkh; l = g_Wkl;   n4 = DD*DD/4;   wantlo = true; }
    else               { src = Wv; h = g_Wvh; l = g_Wvl;   n4 = DD*DD/4;   wantlo = true; }

    const int base = (blockIdx.x * 256 + threadIdx.x) * 4;
    if (base >= n4) return;
    float4 v[4];
    #pragma unroll
    for (int i = 0; i < 4; i++) v[i] = reinterpret_cast<const float4*>(src)[base + i];
    #pragma unroll
    for (int i = 0; i < 4; i++) {
        __half h0 = __float2half_rn(v[i].x), h1 = __float2half_rn(v[i].y);
        __half h2 = __float2half_rn(v[i].z), h3 = __float2half_rn(v[i].w);
        reinterpret_cast<uint2*>(h)[base + i] = make_uint2(pkh(h0, h1), pkh(h2, h3));
        if (wantlo) {
            __half l0 = __float2half_rn(v[i].x - __half2float(h0));
            __half l1 = __float2half_rn(v[i].y - __half2float(h1));
            __half l2 = __float2half_rn(v[i].z - __half2float(h2));
            __half l3 = __float2half_rn(v[i].w - __half2float(h3));
            reinterpret_cast<uint2*>(l)[base + i] = make_uint2(pkh(l0, l1), pkh(l2, l3));
        }
    }
}

// ---------------------------------------------------------------------------
// v [b][s][d] -> vt [b][d][s] (hi and lo)
// ---------------------------------------------------------------------------
__global__ __launch_bounds__(256) void transpose_v() {
    __shared__ __half t[64][65];
    const int b = blockIdx.z, d0 = blockIdx.x * 64, s0 = blockIdx.y * 64;
    const int tid = threadIdx.x;
    const __half* srcs[2] = { g_vh, g_vl };
    __half*       dsts[2] = { g_vth, g_vtl };
    for (int p = 0; p < 2; p++) {
        const __half* src = srcs[p];
        __half* dst = dsts[p];
        for (int i = tid; i < 64 * 64; i += 256) {
            int r = i >> 6, c = i & 63;
            t[r][c] = src[((size_t)b * SS + s0 + r) * DD + d0 + c];
        }
        __syncthreads();
        for (int i = tid; i < 64 * 64; i += 256) {
            int r = i >> 6, c = i & 63;
            dst[((size_t)b * DD + d0 + r) * SS + s0 + c] = t[c][r];
        }
        __syncthreads();
    }
}

// ---------------------------------------------------------------------------
// 2-term fp16 GEMM, NT: C[M,N] = A_h[M,K] * (B_h + B_l)[N,K]^T
//  MODE 5: merged projections (blockIdx.z: 0=q hi-only, 1=k hi+lo, 2=v hi+lo)
//  MODE 3: scores (strictly-upper tiles skipped; scale+mask epilogue)
//  MODE 4: PV (causal K-limit via flags; fp32 out)
// CTA 128x128, 256 threads (2x4 warps, 64x32 warp tile), K-chunk 32,
// 3-stage cp.async pipeline, row stride 80B, ldmatrix fragment loads.
// 2 CTAs per SM (92160B smem each) -> independent barriers overlap stalls.
// ---------------------------------------------------------------------------
#define RS 80
#define BUFB (128 * RS)                // 10240 per buffer
#define STAGEB (3 * BUFB)              // Ah|Bh|Bl = 30720
#define SMEM_DYN (3 * STAGEB)          // 92160

template <int MODE>
__device__ __forceinline__ void stage_cp(
    uint32_t stg, const __half* Ah, const __half* Bh, const __half* Bl,
    int m0, int n0, int k0, int tid)
{
    constexpr int LD = (MODE == 4) ? SS : DD;
    #pragma unroll
    for (int i = 0; i < 2; i++) {
        const int idx = tid + i * 256;              // 512 slots: 128 rows x 4 segs
        const int row = idx >> 2, seg = idx & 3;
        const uint32_t d = (uint32_t)(row * RS + seg * 16);
        const size_t ga = (size_t)(m0 + row) * LD + k0 + seg * 8;
        const size_t gb = (size_t)(n0 + row) * LD + k0 + seg * 8;
        cp16(stg + d,            Ah + ga);
        cp16(stg + BUFB + d,     Bh + gb);
        cp16(stg + 2 * BUFB + d, Bl + gb);
    }
}

template <int MODE>
__global__ void __launch_bounds__(256, 2) gemmX(
    const float* __restrict__ bq, const float* __restrict__ bk,
    const float* __restrict__ bvp, const int* __restrict__ maskp,
    float* __restrict__ outF)
{
    constexpr int KDIM = (MODE == 4) ? SS : DD;

    const int tid = threadIdx.x;
    const int wid = tid >> 5, lane = tid & 31;
    const int g = lane >> 2, t4 = lane & 3;
    const int wm = wid & 1, wn = wid >> 1;          // 2x4 warp grid, 64x32 warp tile
    const int bz = blockIdx.z;
    const int m0 = blockIdx.y * 128, n0 = blockIdx.x * 128;

    // scores: strictly-future tiles never read downstream
    if (MODE == 3 && blockIdx.x > blockIdx.y) return;

    // PV: causal K-limit unless a degenerate row present
    int nch = KDIM / 32;
    if (MODE == 4) {
        __shared__ int s_any;
        if (tid == 0) s_any = 0;
        __syncthreads();
        if (tid < 128 && g_deg[bz * SS + m0 + tid]) s_any = 1;
        __syncthreads();
        if (!s_any) nch = (m0 >> 5) + 4;            // K up to m0+128 only
    }

    const __half *Ah, *Bh, *Bl;
    const float* bias = nullptr;
    __half *oH = nullptr, *oL = nullptr;
    if (MODE == 5) {
        if (bz == 0)      { Ah = g_Qh; Bh = g_Wqh; Bl = g_Wql; bias = bq;  oH = g_qh; }
        else if (bz == 1) { Ah = g_Kh; Bh = g_Wkh; Bl = g_Wkl; bias = bk;  oH = g_kh; oL = g_kl; }
        else              { Ah = g_Vh; Bh = g_Wvh; Bl = g_Wvl; bias = bvp; oH = g_vh; oL = g_vl; }
    } else if (MODE == 3) {
        Ah = g_qh + (size_t)bz * SS * DD;
        Bh = g_kh + (size_t)bz * SS * DD; Bl = g_kl + (size_t)bz * SS * DD;
    } else {
        Ah = g_ph + (size_t)bz * SS * SS;
        Bh = g_vth + (size_t)bz * DD * SS; Bl = g_vtl + (size_t)bz * DD * SS;
    }

    extern __shared__ char dsm[];
    const uint32_t sb = s2u(dsm);

    // ldmatrix lane address components (mapping validated in R9: bit-exact)
    const int part = lane >> 3;
    const int aRow = (part & 1) * 8 + (lane & 7);   // A: m within 16, parts 0/1
    const int aK   = (part >> 1) * 16;              //    k halves 0-7 / 8-15 (bytes)
    const int bRow = (part >> 1) * 8 + (lane & 7);  // B: n within 16, parts 0/2
    const int bK   = (part & 1) * 16;

    float c[4][4][4];
    #pragma unroll
    for (int mt = 0; mt < 4; mt++)
        #pragma unroll
        for (int nt = 0; nt < 4; nt++)
            #pragma unroll
            for (int i = 0; i < 4; i++) c[mt][nt][i] = 0.f;

    // prologue: stages 0, 1 (nch >= 4 always)
    stage_cp<MODE>(sb,          Ah, Bh, Bl, m0, n0, 0,  tid); cp_commit();
    stage_cp<MODE>(sb + STAGEB, Ah, Bh, Bl, m0, n0, 32, tid); cp_commit();

    for (int ch = 0; ch < nch; ch++) {
        if (ch + 2 < nch)
            stage_cp<MODE>(sb + ((ch + 2) % 3) * STAGEB, Ah, Bh, Bl,
                           m0, n0, (ch + 2) * 32, tid);
        cp_commit();
        cp_wait2();
        __syncthreads();

        const uint32_t stg = sb + (ch % 3) * STAGEB;
        const uint32_t sAh = stg;
        const uint32_t sBh = stg + BUFB, sBl = stg + 2 * BUFB;

        #pragma unroll
        for (int kk = 0; kk < 2; kk++) {
            const uint32_t kb = (uint32_t)(kk * 32);
            uint32_t ah[4][4], bh[8], bl[8];
            #pragma unroll
            for (int mt = 0; mt < 4; mt++)
                ldsm4(ah[mt][0], ah[mt][1], ah[mt][2], ah[mt][3],
                      sAh + (uint32_t)((wm * 64 + mt * 16 + aRow) * RS) + aK + kb);
            #pragma unroll
            for (int p = 0; p < 2; p++) {
                const uint32_t br = (uint32_t)((wn * 32 + p * 16 + bRow) * RS) + bK + kb;
                ldsm4(bh[4*p], bh[4*p+1], bh[4*p+2], bh[4*p+3], sBh + br);
                ldsm4(bl[4*p], bl[4*p+1], bl[4*p+2], bl[4*p+3], sBl + br);
            }
            #pragma unroll
            for (int mt = 0; mt < 4; mt++)
                #pragma unroll
                for (int nt = 0; nt < 4; nt++) {
                    mma16816(c[mt][nt], ah[mt], bh + 2 * nt);   // A_h * B_h
                    mma16816(c[mt][nt], ah[mt], bl + 2 * nt);   // A_h * B_l
                }
        }
        __syncthreads();
    }

    // ---- epilogue ----
    #pragma unroll
    for (int mt = 0; mt < 4; mt++) {
        #pragma unroll
        for (int half = 0; half < 2; half++) {
            const int row = m0 + wm * 64 + mt * 16 + g + half * 8;
            #pragma unroll
            for (int nt = 0; nt < 4; nt++) {
                const int cb = n0 + wn * 32 + nt * 8 + t4 * 2;
                float v0 = c[mt][nt][half * 2];
                float v1 = c[mt][nt][half * 2 + 1];
                if (MODE == 5) {
                    v0 += bias[cb]; v1 += bias[cb + 1];
                    __half h0 = __float2half_rn(v0), h1 = __float2half_rn(v1);
                    *reinterpret_cast<uint32_t*>(oH + (size_t)row * DD + cb) = pkh(h0, h1);
                    if (oL) {
                        __half l0 = __float2half_rn(v0 - __half2float(h0));
                        __half l1 = __float2half_rn(v1 - __half2float(h1));
                        *reinterpret_cast<uint32_t*>(oL + (size_t)row * DD + cb) = pkh(l0, l1);
                    }
                } else if (MODE == 3) {
                    const int* mrow = maskp + bz * SS;
                    float s0 = v0 * 0.03125f, s1 = v1 * 0.03125f;
                    if (mrow[cb] == 0)     s0 = NEGV;
                    if (mrow[cb + 1] == 0) s1 = NEGV;
                    if (cb > row)     s0 += NEGV;
                    if (cb + 1 > row) s1 += NEGV;
                    float2 st = make_float2(s0, s1);
                    *reinterpret_cast<float2*>(g_p + (size_t)bz * SS * SS +
                                               (size_t)row * SS + cb) = st;
                } else {
                    float2 st = make_float2(v0, v1);
                    *reinterpret_cast<float2*>(outF + ((size_t)bz * SS + row) * DD + cb) = st;
                }
            }
        }
    }
}

// ---------------------------------------------------------------------------
// Row softmax, causal-restricted (fp32 in, fp16 out).
// Degenerate rows synthesize future scores from the mask (bit-identical).
// ---------------------------------------------------------------------------
__global__ __launch_bounds__(256) void softmax_kernel(const int* __restrict__ maskp) {
    const int row = blockIdx.x;
    const int bz = row >> 11, rloc = row & (SS - 1);
    const float* p = g_p + (size_t)row * SS;
    __half* ph = g_ph + (size_t)row * SS;
    const int tid = threadIdx.x;
    const int csegs = rloc >> 8;

    float v[8];
    float mx = -INFINITY;
    #pragma unroll
    for (int s = 0; s < 8; s++) {
        const int idx = s * 256 + tid;
        v[s] = 0.f;
        if (s <= csegs && idx <= rloc) { v[s] = p[idx]; mx = fmaxf(mx, v[s]); }
    }
    #pragma unroll
    for (int o = 16; o > 0; o >>= 1) mx = fmaxf(mx, __shfl_xor_sync(0xffffffffu, mx, o));

    __shared__ float red[8];
    if ((tid & 31) == 0) red[tid >> 5] = mx;
    __syncthreads();
    float rmax = red[0];
    #pragma unroll
    for (int i = 1; i < 8; i++) rmax = fmaxf(rmax, red[i]);

    const bool deg = (rmax <= -5e9f);
    if (tid == 0) g_deg[row] = deg ? 1 : 0;

    float ssum = 0.f;
    if (!deg) {
        #pragma unroll
        for (int s = 0; s < 8; s++) {
            const int idx = s * 256 + tid;
            float e = 0.f;
            if (s <= csegs && idx <= rloc) e = expf(v[s] - rmax);
            v[s] = e; ssum += e;
        }
    } else {
        const int* mrow = maskp + bz * SS;
        #pragma unroll
        for (int s = 0; s < 8; s++) {
            const int idx = s * 256 + tid;
            float val;
            if (idx <= rloc) val = v[s];
            else             val = (mrow[idx] == 0) ? (NEGV + NEGV) : NEGV;
            float e = expf(val - rmax);
            v[s] = e; ssum += e;
        }
    }
    #pragma unroll
    for (int o = 16; o > 0; o >>= 1) ssum += __shfl_xor_sync(0xffffffffu, ssum, o);
    __syncthreads();
    if ((tid & 31) == 0) red[tid >> 5] = ssum;
    __syncthreads();
    float tot = 0.f;
    #pragma unroll
    for (int i = 0; i < 8; i++) tot += red[i];

    const float inv = 1.0f / tot;
    #pragma unroll
    for (int s = 0; s < 8; s++)
        ph[s * 256 + tid] = __float2half_rn(v[s] * inv);
}

// ---------------------------------------------------------------------------
extern "C" void kernel_launch(void* const* d_in, const int* in_sizes, int n_in,
                              void* d_out, int out_size)
{
    (void)in_sizes; (void)n_in; (void)out_size;
    const float* Q    = (const float*)d_in[0];
    const float* Kin  = (const float*)d_in[1];
    const float* Vin  = (const float*)d_in[2];
    const int*   mask = (const int*)  d_in[3];
    const float* Wq   = (const float*)d_in[4];
    const float* bq   = (const float*)d_in[5];
    const float* Wk   = (const float*)d_in[6];
    const float* bk   = (const float*)d_in[7];
    const float* Wv   = (const float*)d_in[8];
    const float* bv   = (const float*)d_in[9];
    float* out = (float*)d_out;

    cudaFuncSetAttribute(gemmX<5>, cudaFuncAttributeMaxDynamicSharedMemorySize, SMEM_DYN);
    cudaFuncSetAttribute(gemmX<3>, cudaFuncAttributeMaxDynamicSharedMemorySize, SMEM_DYN);
    cudaFuncSetAttribute(gemmX<4>, cudaFuncAttributeMaxDynamicSharedMemorySize, SMEM_DYN);

    // 1) fp16 conversion (QKV hi-only, weights hi+lo)
    cvt_all<<<dim3(2048, 6), 256>>>(Q, Kin, Vin, Wq, Wk, Wv);
    // 2) merged q/k/v projections: M = 8192, N = 1024, z = tensor select
    gemmX<5><<<dim3(8, 64, 3), 256, SMEM_DYN>>>(bq, bk, bv, nullptr, nullptr);
    // 3) v transpose
    transpose_v<<<dim3(16, 32, NB), 256>>>();
    // 4) scores (4th launch -> profiled): per-batch 2048x2048, K = 1024
    gemmX<3><<<dim3(16, 16, NB), 256, SMEM_DYN>>>(nullptr, nullptr, nullptr, mask, nullptr);
    // 5) softmax (causal-restricted, sets degeneracy flags)
    softmax_kernel<<<NB * SS, 256>>>(mask);
    // 6) O = P @ V : per-batch 2048 x 1024, K causal-limited
    gemmX<4><<<dim3(8, 16, NB), 256, SMEM_DYN>>>(nullptr, nullptr, nullptr, nullptr, out);
}

// round 11
// speedup vs baseline: 3.1528x; 1.1288x over previous
#include <cuda_runtime.h>
#include <cuda_fp16.h>
#include <cstdint>
#include <math.h>

#define NB 4
#define SS 2048
#define DD 1024
#define NEGV (-1e10f)

// ---------------------------------------------------------------------------
// Device-global scratch. fp16 2-term split: C = A_h * (B_h + B_l).
// ---------------------------------------------------------------------------
__device__ __align__(128) __half g_Qh[NB*SS*DD];
__device__ __align__(128) __half g_Kh[NB*SS*DD];
__device__ __align__(128) __half g_Vh[NB*SS*DD];
__device__ __align__(128) __half g_Wqh[DD*DD], g_Wql[DD*DD];
__device__ __align__(128) __half g_Wkh[DD*DD], g_Wkl[DD*DD];
__device__ __align__(128) __half g_Wvh[DD*DD], g_Wvl[DD*DD];
__device__ __align__(128) __half g_qh[NB*SS*DD];
__device__ __align__(128) __half g_kh[NB*SS*DD], g_kl[NB*SS*DD];
__device__ __align__(128) __half g_vh[NB*SS*DD], g_vl[NB*SS*DD];
// compacted (allowed columns only, zero-padded)
__device__ __align__(128) __half g_kc[NB*SS*DD], g_kcl[NB*SS*DD];
__device__ __align__(128) __half g_vc[NB*SS*DD], g_vcl[NB*SS*DD];
__device__ __align__(128) __half g_vth[NB*DD*SS], g_vtl[NB*DD*SS];  // vtc [b][d][j]
__device__ float  g_p[(size_t)NB*SS*SS];
__device__ __align__(128) __half g_ph[(size_t)NB*SS*SS];
__device__ int    g_deg[NB*SS];
__device__ int    g_idx[NB*2048];     // allowed-col indices (sentinel 4096 beyond cnt)
__device__ int    g_cnt[NB];
__device__ int    g_clim[NB*16];      // #allowed cols <= mb*128+127

// ---------------------------------------------------------------------------
// helpers
// ---------------------------------------------------------------------------
__device__ __forceinline__ uint32_t s2u(const void* p) {
    return (uint32_t)__cvta_generic_to_shared(p);
}
__device__ __forceinline__ void cp16(uint32_t dst, const void* src) {
    asm volatile("cp.async.cg.shared.global [%0], [%1], 16;\n"
                 :: "r"(dst), "l"(src) : "memory");
}
__device__ __forceinline__ void cp_commit() {
    asm volatile("cp.async.commit_group;\n" ::: "memory");
}
__device__ __forceinline__ void cp_wait2() {
    asm volatile("cp.async.wait_group 2;\n" ::: "memory");
}
__device__ __forceinline__ void ldsm4(uint32_t& r0, uint32_t& r1, uint32_t& r2,
                                      uint32_t& r3, uint32_t a) {
    asm volatile("ldmatrix.sync.aligned.m8n8.x4.shared.b16 {%0,%1,%2,%3}, [%4];"
        : "=r"(r0), "=r"(r1), "=r"(r2), "=r"(r3) : "r"(a));
}
__device__ __forceinline__ void mma16816(float* c, const uint32_t* a, const uint32_t* b) {
    asm volatile("mma.sync.aligned.m16n8k16.row.col.f32.f16.f16.f32 "
        "{%0,%1,%2,%3}, {%4,%5,%6,%7}, {%8,%9}, {%0,%1,%2,%3};"
        : "+f"(c[0]), "+f"(c[1]), "+f"(c[2]), "+f"(c[3])
        : "r"(a[0]), "r"(a[1]), "r"(a[2]), "r"(a[3]), "r"(b[0]), "r"(b[1]));
}
__device__ __forceinline__ uint32_t pkh(__half a, __half b) {
    __half2 t = __halves2half2(a, b);
    return *reinterpret_cast<uint32_t*>(&t);
}

// ---------------------------------------------------------------------------
// One-shot fp32 -> fp16 conversion. QKV: hi only. Weights: hi + lo. MLP=4.
// ---------------------------------------------------------------------------
__global__ __launch_bounds__(256) void cvt_all(
    const float* __restrict__ Q, const float* __restrict__ K,
    const float* __restrict__ V, const float* __restrict__ Wq,
    const float* __restrict__ Wk, const float* __restrict__ Wv)
{
    const int seg = blockIdx.y;
    const float* src; __half *h, *l; int n4; bool wantlo;
    if      (seg == 0) { src = Q;  h = g_Qh;  l = nullptr; n4 = NB*SS*DD/4; wantlo = false; }
    else if (seg == 1) { src = K;  h = g_Kh;  l = nullptr; n4 = NB*SS*DD/4; wantlo = false; }
    else if (seg == 2) { src = V;  h = g_Vh;  l = nullptr; n4 = NB*SS*DD/4; wantlo = false; }
    else if (seg == 3) { src = Wq; h = g_Wqh; l = g_Wql;   n4 = DD*DD/4;   wantlo = true; }
    else if (seg == 4) { src = Wk; h = g_Wkh; l = g_Wkl;   n4 = DD*DD/4;   wantlo = true; }
    else               { src = Wv; h = g_Wvh; l = g_Wvl;   n4 = DD*DD/4;   wantlo = true; }

    const int base = (blockIdx.x * 256 + threadIdx.x) * 4;
    if (base >= n4) return;
    float4 v[4];
    #pragma unroll
    for (int i = 0; i < 4; i++) v[i] = reinterpret_cast<const float4*>(src)[base + i];
    #pragma unroll
    for (int i = 0; i < 4; i++) {
        __half h0 = __float2half_rn(v[i].x), h1 = __float2half_rn(v[i].y);
        __half h2 = __float2half_rn(v[i].z), h3 = __float2half_rn(v[i].w);
        reinterpret_cast<uint2*>(h)[base + i] = make_uint2(pkh(h0, h1), pkh(h2, h3));
        if (wantlo) {
            __half l0 = __float2half_rn(v[i].x - __half2float(h0));
            __half l1 = __float2half_rn(v[i].y - __half2float(h1));
            __half l2 = __float2half_rn(v[i].z - __half2float(h2));
            __half l3 = __float2half_rn(v[i].w - __half2float(h3));
            reinterpret_cast<uint2*>(l)[base + i] = make_uint2(pkh(l0, l1), pkh(l2, l3));
        }
    }
}

// ---------------------------------------------------------------------------
// Per-batch allowed-column index list + prefix tables (one block per batch).
// ---------------------------------------------------------------------------
__global__ __launch_bounds__(256) void compact_build(const int* __restrict__ maskp) {
    const int b = blockIdx.x;
    const int tid = threadIdx.x;
    __shared__ int s_m[2048];
    __shared__ int s_tot[256];
    for (int i = tid; i < 2048; i += 256) s_m[i] = (maskp[b * SS + i] != 0) ? 1 : 0;
    __syncthreads();
    const int base = tid * 8;
    int loc[8]; int sum = 0;
    #pragma unroll
    for (int k = 0; k < 8; k++) { loc[k] = sum; sum += s_m[base + k]; }
    s_tot[tid] = sum;
    __syncthreads();
    // Hillis-Steele inclusive scan over 256 thread totals
    for (int off = 1; off < 256; off <<= 1) {
        int v = (tid >= off) ? s_tot[tid - off] : 0;
        __syncthreads();
        s_tot[tid] += v;
        __syncthreads();
    }
    const int excl = (tid == 0) ? 0 : s_tot[tid - 1];
    #pragma unroll
    for (int k = 0; k < 8; k++)
        if (s_m[base + k]) g_idx[b * 2048 + excl + loc[k]] = base + k;
    const int cnt = s_tot[255];
    if (tid < 16) g_clim[b * 16 + tid] = s_tot[(tid + 1) * 16 - 1];  // prefix at (tid+1)*128
    if (tid == 0) g_cnt[b] = cnt;
    for (int j = cnt + tid; j < 2048; j += 256) g_idx[b * 2048 + j] = 4096;
}

// ---------------------------------------------------------------------------
// Gather compacted k/v rows (zero-pad beyond cnt). One block per (j, b).
// ---------------------------------------------------------------------------
__global__ __launch_bounds__(128) void gather_kv() {
    const int b = blockIdx.y, j = blockIdx.x;
    const int tid = threadIdx.x;
    const int cnt = g_cnt[b];
    const size_t doff = ((size_t)b * SS + j) * DD;
    uint4* dkc  = reinterpret_cast<uint4*>(g_kc  + doff);
    uint4* dkcl = reinterpret_cast<uint4*>(g_kcl + doff);
    uint4* dvc  = reinterpret_cast<uint4*>(g_vc  + doff);
    uint4* dvcl = reinterpret_cast<uint4*>(g_vcl + doff);
    if (j >= cnt) {
        const uint4 z = make_uint4(0, 0, 0, 0);
        for (int t = tid; t < 128; t += 128) { dkc[t] = z; dkcl[t] = z; dvc[t] = z; dvcl[t] = z; }
        return;
    }
    const int src = g_idx[b * 2048 + j];
    const size_t soff = ((size_t)b * SS + src) * DD;
    const uint4* skh = reinterpret_cast<const uint4*>(g_kh + soff);
    const uint4* skl = reinterpret_cast<const uint4*>(g_kl + soff);
    const uint4* svh = reinterpret_cast<const uint4*>(g_vh + soff);
    const uint4* svl = reinterpret_cast<const uint4*>(g_vl + soff);
    for (int t = tid; t < 128; t += 128) {
        dkc[t] = skh[t]; dkcl[t] = skl[t]; dvc[t] = svh[t]; dvcl[t] = svl[t];
    }
}

// ---------------------------------------------------------------------------
// compacted v [b][j][d] -> vt [b][d][j] (hi and lo)
// ---------------------------------------------------------------------------
__global__ __launch_bounds__(256) void transpose_v() {
    __shared__ __half t[64][65];
    const int b = blockIdx.z, d0 = blockIdx.x * 64, s0 = blockIdx.y * 64;
    const int tid = threadIdx.x;
    const __half* srcs[2] = { g_vc, g_vcl };
    __half*       dsts[2] = { g_vth, g_vtl };
    for (int p = 0; p < 2; p++) {
        const __half* src = srcs[p];
        __half* dst = dsts[p];
        for (int i = tid; i < 64 * 64; i += 256) {
            int r = i >> 6, c = i & 63;
            t[r][c] = src[((size_t)b * SS + s0 + r) * DD + d0 + c];
        }
        __syncthreads();
        for (int i = tid; i < 64 * 64; i += 256) {
            int r = i >> 6, c = i & 63;
            dst[((size_t)b * DD + d0 + r) * SS + s0 + c] = t[c][r];
        }
        __syncthreads();
    }
}

// ---------------------------------------------------------------------------
// 2-term fp16 GEMM, NT. CTA 128x128, 256 threads (2x4 warps), K-chunk 32,
// 3-stage cp.async pipeline, RS=80, ldmatrix. 2 CTAs per SM.
//  MODE 5: merged projections (z: 0=q hi-only, 1=k hi+lo, 2=v hi+lo)
//  MODE 3: scores in COMPACTED col space (future tiles -> constants)
//  MODE 4: PV over compacted K (per-block limit; fp32 out)
// ---------------------------------------------------------------------------
#define RS 80
#define BUFB (128 * RS)
#define STAGEB (3 * BUFB)
#define SMEM_DYN (3 * STAGEB)          // 92160

template <int MODE>
__device__ __forceinline__ void stage_cp(
    uint32_t stg, const __half* Ah, const __half* Bh, const __half* Bl,
    int m0, int n0, int k0, int tid)
{
    constexpr int LD = (MODE == 4) ? SS : DD;
    #pragma unroll
    for (int i = 0; i < 2; i++) {
        const int idx = tid + i * 256;
        const int row = idx >> 2, seg = idx & 3;
        const uint32_t d = (uint32_t)(row * RS + seg * 16);
        const size_t ga = (size_t)(m0 + row) * LD + k0 + seg * 8;
        const size_t gb = (size_t)(n0 + row) * LD + k0 + seg * 8;
        cp16(stg + d,            Ah + ga);
        cp16(stg + BUFB + d,     Bh + gb);
        cp16(stg + 2 * BUFB + d, Bl + gb);
    }
}

template <int MODE>
__global__ void __launch_bounds__(256, 2) gemmX(
    const float* __restrict__ bq, const float* __restrict__ bk,
    const float* __restrict__ bvp, float* __restrict__ outF)
{
    constexpr int KDIM = (MODE == 4) ? SS : DD;

    const int tid = threadIdx.x;
    const int wid = tid >> 5, lane = tid & 31;
    const int g = lane >> 2, t4 = lane & 3;
    const int wm = wid & 1, wn = wid >> 1;          // 2x4 warps, 64x32 warp tile
    const int bz = blockIdx.z;
    const int m0 = blockIdx.y * 128, n0 = blockIdx.x * 128;

    int cnt = 0, PN = 0;
    if (MODE == 3 || MODE == 4) {
        cnt = g_cnt[bz];
        PN = (cnt + 127) & ~127;
    }

    // ---- scores: compacted-space early paths ----
    if (MODE == 3) {
        if (n0 >= PN) return;
        const int i0 = g_idx[bz * 2048 + n0];
        if (i0 > m0 + 127) {
            // entire tile future for every row in block: constants
            const int cj = (tid & 31) * 4;
            float4 w;
            w.x = (n0 + cj + 0 < cnt) ? NEGV : (NEGV + NEGV);
            w.y = (n0 + cj + 1 < cnt) ? NEGV : (NEGV + NEGV);
            w.z = (n0 + cj + 2 < cnt) ? NEGV : (NEGV + NEGV);
            w.w = (n0 + cj + 3 < cnt) ? NEGV : (NEGV + NEGV);
            float* dst = g_p + (size_t)bz * SS * SS + (size_t)m0 * SS + n0;
            #pragma unroll
            for (int r = tid >> 5; r < 128; r += 8)
                *reinterpret_cast<float4*>(dst + (size_t)r * SS + cj) = w;
            return;
        }
    }

    // ---- PV: compacted K-limit ----
    int nch = KDIM / 32;
    if (MODE == 4) {
        __shared__ int s_any;
        if (tid == 0) s_any = 0;
        __syncthreads();
        if (tid < 128 && g_deg[bz * SS + m0 + tid]) s_any = 1;
        __syncthreads();
        const int limit = s_any ? PN : g_clim[bz * 16 + (m0 >> 7)];
        nch = (limit + 31) >> 5;
        if (nch < 2) nch = 2;                       // prologue depth (PN >= 128)
    }

    const __half *Ah, *Bh, *Bl;
    const float* bias = nullptr;
    __half *oH = nullptr, *oL = nullptr;
    if (MODE == 5) {
        if (bz == 0)      { Ah = g_Qh; Bh = g_Wqh; Bl = g_Wql; bias = bq;  oH = g_qh; }
        else if (bz == 1) { Ah = g_Kh; Bh = g_Wkh; Bl = g_Wkl; bias = bk;  oH = g_kh; oL = g_kl; }
        else              { Ah = g_Vh; Bh = g_Wvh; Bl = g_Wvl; bias = bvp; oH = g_vh; oL = g_vl; }
    } else if (MODE == 3) {
        Ah = g_qh + (size_t)bz * SS * DD;
        Bh = g_kc + (size_t)bz * SS * DD; Bl = g_kcl + (size_t)bz * SS * DD;
    } else {
        Ah = g_ph + (size_t)bz * SS * SS;
        Bh = g_vth + (size_t)bz * DD * SS; Bl = g_vtl + (size_t)bz * DD * SS;
    }

    extern __shared__ char dsm[];
    const uint32_t sb = s2u(dsm);

    const int part = lane >> 3;
    const int aRow = (part & 1) * 8 + (lane & 7);
    const int aK   = (part >> 1) * 16;
    const int bRow = (part >> 1) * 8 + (lane & 7);
    const int bK   = (part & 1) * 16;

    float c[4][4][4];
    #pragma unroll
    for (int mt = 0; mt < 4; mt++)
        #pragma unroll
        for (int nt = 0; nt < 4; nt++)
            #pragma unroll
            for (int i = 0; i < 4; i++) c[mt][nt][i] = 0.f;

    stage_cp<MODE>(sb,          Ah, Bh, Bl, m0, n0, 0,  tid); cp_commit();
    stage_cp<MODE>(sb + STAGEB, Ah, Bh, Bl, m0, n0, 32, tid); cp_commit();

    for (int ch = 0; ch < nch; ch++) {
        if (ch + 2 < nch)
            stage_cp<MODE>(sb + ((ch + 2) % 3) * STAGEB, Ah, Bh, Bl,
                           m0, n0, (ch + 2) * 32, tid);
        cp_commit();
        cp_wait2();
        __syncthreads();

        const uint32_t stg = sb + (ch % 3) * STAGEB;
        const uint32_t sAh = stg;
        const uint32_t sBh = stg + BUFB, sBl = stg + 2 * BUFB;

        #pragma unroll
        for (int kk = 0; kk < 2; kk++) {
            const uint32_t kb = (uint32_t)(kk * 32);
            uint32_t ah[4][4], bh[8], bl[8];
            #pragma unroll
            for (int mt = 0; mt < 4; mt++)
                ldsm4(ah[mt][0], ah[mt][1], ah[mt][2], ah[mt][3],
                      sAh + (uint32_t)((wm * 64 + mt * 16 + aRow) * RS) + aK + kb);
            #pragma unroll
            for (int p = 0; p < 2; p++) {
                const uint32_t br = (uint32_t)((wn * 32 + p * 16 + bRow) * RS) + bK + kb;
                ldsm4(bh[4*p], bh[4*p+1], bh[4*p+2], bh[4*p+3], sBh + br);
                ldsm4(bl[4*p], bl[4*p+1], bl[4*p+2], bl[4*p+3], sBl + br);
            }
            #pragma unroll
            for (int mt = 0; mt < 4; mt++)
                #pragma unroll
                for (int nt = 0; nt < 4; nt++) {
                    mma16816(c[mt][nt], ah[mt], bh + 2 * nt);
                    mma16816(c[mt][nt], ah[mt], bl + 2 * nt);
                }
        }
        __syncthreads();
    }

    // ---- epilogue ----
    #pragma unroll
    for (int mt = 0; mt < 4; mt++) {
        #pragma unroll
        for (int half = 0; half < 2; half++) {
            const int row = m0 + wm * 64 + mt * 16 + g + half * 8;
            #pragma unroll
            for (int nt = 0; nt < 4; nt++) {
                const int cb = n0 + wn * 32 + nt * 8 + t4 * 2;
                float v0 = c[mt][nt][half * 2];
                float v1 = c[mt][nt][half * 2 + 1];
                if (MODE == 5) {
                    v0 += bias[cb]; v1 += bias[cb + 1];
                    __half h0 = __float2half_rn(v0), h1 = __float2half_rn(v1);
                    *reinterpret_cast<uint32_t*>(oH + (size_t)row * DD + cb) = pkh(h0, h1);
                    if (oL) {
                        __half l0 = __float2half_rn(v0 - __half2float(h0));
                        __half l1 = __float2half_rn(v1 - __half2float(h1));
                        *reinterpret_cast<uint32_t*>(oL + (size_t)row * DD + cb) = pkh(l0, l1);
                    }
                } else if (MODE == 3) {
                    const int i0 = g_idx[bz * 2048 + cb];
                    const int i1 = g_idx[bz * 2048 + cb + 1];
                    float s0, s1;
                    if (cb >= cnt)          s0 = NEGV + NEGV;
                    else if (i0 > row)      s0 = NEGV;
                    else                    s0 = v0 * 0.03125f;
                    if (cb + 1 >= cnt)      s1 = NEGV + NEGV;
                    else if (i1 > row)      s1 = NEGV;
                    else                    s1 = v1 * 0.03125f;
                    float2 st = make_float2(s0, s1);
                    *reinterpret_cast<float2*>(g_p + (size_t)bz * SS * SS +
                                               (size_t)row * SS + cb) = st;
                } else {
                    float2 st = make_float2(v0, v1);
                    *reinterpret_cast<float2*>(outF + ((size_t)bz * SS + row) * DD + cb) = st;
                }
            }
        }
    }
}

// ---------------------------------------------------------------------------
// Row softmax over compacted width PN. Values are self-contained:
// causal-allowed = real score, future-allowed = NEG, pads = 2*NEG.
// Degenerate rows (rmax = NEG) fall out automatically (uniform over future).
// ---------------------------------------------------------------------------
__global__ __launch_bounds__(256) void softmax_kernel() {
    const int row = blockIdx.x;
    const int bz = row >> 11;
    const int cnt = g_cnt[bz];
    const int PN = (cnt + 127) & ~127;
    const float* p = g_p + (size_t)row * SS;
    __half* ph = g_ph + (size_t)row * SS;
    const int tid = threadIdx.x;

    float v[8];
    float mx = -INFINITY;
    #pragma unroll
    for (int s = 0; s < 8; s++) {
        const int idx = s * 256 + tid;
        v[s] = -INFINITY;
        if (idx < PN) { v[s] = p[idx]; mx = fmaxf(mx, v[s]); }
    }
    #pragma unroll
    for (int o = 16; o > 0; o >>= 1) mx = fmaxf(mx, __shfl_xor_sync(0xffffffffu, mx, o));

    __shared__ float red[8];
    if ((tid & 31) == 0) red[tid >> 5] = mx;
    __syncthreads();
    float rmax = red[0];
    #pragma unroll
    for (int i = 1; i < 8; i++) rmax = fmaxf(rmax, red[i]);

    if (tid == 0) g_deg[row] = (rmax <= -5e9f) ? 1 : 0;

    float ssum = 0.f;
    #pragma unroll
    for (int s = 0; s < 8; s++) {
        const int idx = s * 256 + tid;
        float e = 0.f;
        if (idx < PN) e = __expf(v[s] - rmax);
        v[s] = e; ssum += e;
    }
    #pragma unroll
    for (int o = 16; o > 0; o >>= 1) ssum += __shfl_xor_sync(0xffffffffu, ssum, o);
    __syncthreads();
    if ((tid & 31) == 0) red[tid >> 5] = ssum;
    __syncthreads();
    float tot = 0.f;
    #pragma unroll
    for (int i = 0; i < 8; i++) tot += red[i];

    const float inv = 1.0f / tot;
    #pragma unroll
    for (int s = 0; s < 8; s++) {
        const int idx = s * 256 + tid;
        if (idx < PN) ph[idx] = __float2half_rn(v[s] * inv);
    }
}

// ---------------------------------------------------------------------------
extern "C" void kernel_launch(void* const* d_in, const int* in_sizes, int n_in,
                              void* d_out, int out_size)
{
    (void)in_sizes; (void)n_in; (void)out_size;
    const float* Q    = (const float*)d_in[0];
    const float* Kin  = (const float*)d_in[1];
    const float* Vin  = (const float*)d_in[2];
    const int*   mask = (const int*)  d_in[3];
    const float* Wq   = (const float*)d_in[4];
    const float* bq   = (const float*)d_in[5];
    const float* Wk   = (const float*)d_in[6];
    const float* bk   = (const float*)d_in[7];
    const float* Wv   = (const float*)d_in[8];
    const float* bv   = (const float*)d_in[9];
    float* out = (float*)d_out;

    cudaFuncSetAttribute(gemmX<5>, cudaFuncAttributeMaxDynamicSharedMemorySize, SMEM_DYN);
    cudaFuncSetAttribute(gemmX<3>, cudaFuncAttributeMaxDynamicSharedMemorySize, SMEM_DYN);
    cudaFuncSetAttribute(gemmX<4>, cudaFuncAttributeMaxDynamicSharedMemorySize, SMEM_DYN);

    // 1) fp16 conversion (QKV hi-only, weights hi+lo)
    cvt_all<<<dim3(2048, 6), 256>>>(Q, Kin, Vin, Wq, Wk, Wv);
    // 2) allowed-column index lists + prefix tables
    compact_build<<<NB, 256>>>(mask);
    // 3) merged q/k/v projections
    gemmX<5><<<dim3(8, 64, 3), 256, SMEM_DYN>>>(bq, bk, bv, nullptr);
    // 4) gather compacted k/v rows
    gather_kv<<<dim3(2048, NB), 128>>>();
    // 5) transpose compacted v
    transpose_v<<<dim3(16, 32, NB), 256>>>();
    // 6) scores in compacted space
    gemmX<3><<<dim3(16, 16, NB), 256, SMEM_DYN>>>(nullptr, nullptr, nullptr, nullptr);
    // 7) softmax over compacted width (sets degeneracy flags)
    softmax_kernel<<<NB * SS, 256>>>();
    // 8) O = P @ Vc over compacted K
    gemmX<4><<<dim3(8, 16, NB), 256, SMEM_DYN>>>(nullptr, nullptr, nullptr, out);
}